// round 9
// baseline (speedup 1.0000x reference)
#include <cuda_runtime.h>
#include <cuda_bf16.h>
#include <math.h>
#include <stdint.h>

#define D_      1024
#define S_      8192
#define B_      4
#define NROWS   (B_ * S_)      // 32768
#define E3      (3 * D_)       // 3072

// ---------------- scratch (static __device__: allocation-free) ----------------
__device__ __nv_bfloat16 g_Xn  [(size_t)NROWS * D_];   // 64 MiB
__device__ __nv_bfloat16 g_Win [(size_t)E3 * D_];      // 6 MiB
__device__ __nv_bfloat16 g_Wpr [(size_t)B_ * D_ * D_]; // 8 MiB  (A-scaled W_out, per batch)
__device__ __nv_bfloat16 g_Qb  [(size_t)NROWS * D_];   // 64 MiB
__device__ __nv_bfloat16 g_Kb  [(size_t)NROWS * D_];   // 64 MiB
__device__ __nv_bfloat16 g_Vb  [(size_t)NROWS * D_];   // 64 MiB
__device__ float         g_npQ [(size_t)NROWS * 16];   // 2 MiB  (per-row sq-norm partials)
__device__ float         g_npK [(size_t)NROWS * 16];   // 2 MiB
__device__ float         g_Apart[(size_t)4096 * D_];   // 16 MiB (per-warp partials)
__device__ float         g_A8  [8 * B_ * D_];
__device__ __nv_bfloat16 g_Y   [(size_t)NROWS * D_];   // 64 MiB (Qhat, bf16)

__device__ __forceinline__ uint32_t smem_u32(const void* p) {
    uint32_t a;
    asm("{ .reg .u64 t; cvta.to.shared.u64 t, %1; cvt.u32.u64 %0, t; }" : "=r"(a) : "l"(p));
    return a;
}

// ---------------- fp32 -> bf16 weight conversion (W_in) ----------------
__global__ void k_convert(const float* __restrict__ src, int n)
{
    int i = (blockIdx.x * blockDim.x + threadIdx.x) * 4;
    if (i >= n) return;
    float4 v = *(const float4*)(src + i);
    *(__nv_bfloat162*)(g_Win + i)     = __floats2bfloat162_rn(v.x, v.y);
    *(__nv_bfloat162*)(g_Win + i + 2) = __floats2bfloat162_rn(v.z, v.w);
}

// ---------------- LayerNorm: warp-per-row, no barriers ----------------
__global__ void __launch_bounds__(256) k_layernorm(
    const float* __restrict__ X, const float* __restrict__ lg, const float* __restrict__ lb)
{
    const int w    = threadIdx.x >> 5;
    const int lane = threadIdx.x & 31;
    const int row  = blockIdx.x * 8 + w;
    const int c0   = 4 * lane;
    const float* xp = X + (size_t)row * D_ + c0;

    float x[8][4];
    float s = 0.f, sq = 0.f;
    #pragma unroll
    for (int k = 0; k < 8; k++) {
        float4 v = *(const float4*)(xp + 128 * k);
        x[k][0] = v.x; x[k][1] = v.y; x[k][2] = v.z; x[k][3] = v.w;
        s  += v.x + v.y + v.z + v.w;
        sq += v.x * v.x + v.y * v.y + v.z * v.z + v.w * v.w;
    }
    #pragma unroll
    for (int o = 16; o; o >>= 1) {
        s  += __shfl_xor_sync(0xffffffffu, s, o);
        sq += __shfl_xor_sync(0xffffffffu, sq, o);
    }
    const float mu  = s * (1.f / D_);
    const float var = sq * (1.f / D_) - mu * mu;
    const float rs  = rsqrtf(var + 1e-5f);

    __nv_bfloat16* op = g_Xn + (size_t)row * D_ + c0;
    #pragma unroll
    for (int k = 0; k < 8; k++) {
        float4 g4 = *(const float4*)(lg + c0 + 128 * k);
        float4 b4 = *(const float4*)(lb + c0 + 128 * k);
        float y0 = (x[k][0] - mu) * rs * g4.x + b4.x;
        float y1 = (x[k][1] - mu) * rs * g4.y + b4.y;
        float y2 = (x[k][2] - mu) * rs * g4.z + b4.z;
        float y3 = (x[k][3] - mu) * rs * g4.w + b4.w;
        *(__nv_bfloat162*)(op + 128 * k)     = __floats2bfloat162_rn(y0, y1);
        *(__nv_bfloat162*)(op + 128 * k + 2) = __floats2bfloat162_rn(y2, y3);
    }
}

// ---------------- mma.sync bf16 GEMM ----------------
// 128x256 block tile, 8 warps (2m x 4n), warp tile 64x64, KC=64, 4-stage cp.async.
// mode 0: A=g_Xn, B=g_Win; C -> g_Qb/g_Kb/g_Vb (bf16; Q/K also write norm partials)
// mode 1: A=g_Y,  B=g_Wpr[batch]; C -> out (fp32, += X)
#define KC 64
#define NCHUNK 16
#define ASTAGE 16384
#define BSTAGE 32768
#define STAGE_BYTES (ASTAGE + BSTAGE)     // 48 KB
#define GEMM_SMEM (4 * STAGE_BYTES)       // 192 KB

__global__ void __launch_bounds__(256, 1) k_gemm(
    const float* __restrict__ addX, float* __restrict__ Cout, int mode)
{
    extern __shared__ char smem[];
    const int K = 1024;
    const int tid  = threadIdx.x;
    const int w    = tid >> 5;
    const int lane = tid & 31;
    const int wm   = w & 1;
    const int wn   = w >> 1;
    const int m0 = blockIdx.y * 128;
    const int n0 = blockIdx.x * 256;

    const __nv_bfloat16* Ag = mode ? g_Y : g_Xn;
    const __nv_bfloat16* Bg = mode ? (g_Wpr + (size_t)(m0 >> 13) * D_ * D_) : g_Win;

    const uint32_t sbase = smem_u32(smem);

    auto issue = [&](int kt) {
        const uint32_t st = sbase + (kt & 3) * STAGE_BYTES;
        #pragma unroll
        for (int i = 0; i < 12; i++) {
            int vec = i * 256 + tid;
            int isB = vec >= 1024;
            int vv  = isB ? vec - 1024 : vec;
            int row = vv >> 3;
            int c   = vv & 7;
            const __nv_bfloat16* src =
                (isB ? Bg + (size_t)(n0 + row) * K : Ag + (size_t)(m0 + row) * K)
                + kt * KC + c * 8;
            uint32_t dst = st + (isB ? ASTAGE : 0) + row * 128 + (((c ^ (row & 7)) << 4));
            asm volatile("cp.async.cg.shared.global [%0], [%1], 16;" :: "r"(dst), "l"(src));
        }
        asm volatile("cp.async.commit_group;" ::: "memory");
    };

    float acc[4][8][4];
    #pragma unroll
    for (int mi = 0; mi < 4; mi++)
        #pragma unroll
        for (int ni = 0; ni < 8; ni++)
            #pragma unroll
            for (int e = 0; e < 4; e++) acc[mi][ni][e] = 0.f;

    issue(0); issue(1); issue(2);

    const int lr = lane & 15;
    const int lc = lane >> 4;

    uint32_t a[2][4][4], b[2][8][2];

    for (int kt = 0; kt < NCHUNK; kt++) {
        asm volatile("cp.async.wait_group 2;" ::: "memory");
        __syncthreads();
        if (kt + 3 < NCHUNK) issue(kt + 3);
        else asm volatile("cp.async.commit_group;" ::: "memory");

        const uint32_t sA = sbase + (kt & 3) * STAGE_BYTES;
        const uint32_t sB = sA + ASTAGE;

        {
            const int c = lc;
            #pragma unroll
            for (int mi = 0; mi < 4; mi++) {
                int r = wm * 64 + mi * 16 + lr;
                uint32_t addr = sA + r * 128 + ((c ^ (r & 7)) << 4);
                asm volatile("ldmatrix.sync.aligned.m8n8.x4.shared.b16 {%0,%1,%2,%3}, [%4];"
                    : "=r"(a[0][mi][0]), "=r"(a[0][mi][1]), "=r"(a[0][mi][2]), "=r"(a[0][mi][3])
                    : "r"(addr));
            }
            #pragma unroll
            for (int nb = 0; nb < 4; nb++) {
                int r = wn * 64 + nb * 16 + lr;
                uint32_t addr = sB + r * 128 + ((c ^ (r & 7)) << 4);
                uint32_t t0, t1, t2, t3;
                asm volatile("ldmatrix.sync.aligned.m8n8.x4.shared.b16 {%0,%1,%2,%3}, [%4];"
                    : "=r"(t0), "=r"(t1), "=r"(t2), "=r"(t3) : "r"(addr));
                b[0][nb * 2][0] = t0; b[0][nb * 2][1] = t2;
                b[0][nb * 2 + 1][0] = t1; b[0][nb * 2 + 1][1] = t3;
            }
        }

        #pragma unroll
        for (int ks = 0; ks < 4; ks++) {
            const int cur = ks & 1;
            const int nxt = cur ^ 1;
            if (ks < 3) {
                const int c = (ks + 1) * 2 + lc;
                #pragma unroll
                for (int mi = 0; mi < 4; mi++) {
                    int r = wm * 64 + mi * 16 + lr;
                    uint32_t addr = sA + r * 128 + ((c ^ (r & 7)) << 4);
                    asm volatile("ldmatrix.sync.aligned.m8n8.x4.shared.b16 {%0,%1,%2,%3}, [%4];"
                        : "=r"(a[nxt][mi][0]), "=r"(a[nxt][mi][1]),
                          "=r"(a[nxt][mi][2]), "=r"(a[nxt][mi][3]) : "r"(addr));
                }
                #pragma unroll
                for (int nb = 0; nb < 4; nb++) {
                    int r = wn * 64 + nb * 16 + lr;
                    uint32_t addr = sB + r * 128 + ((c ^ (r & 7)) << 4);
                    uint32_t t0, t1, t2, t3;
                    asm volatile("ldmatrix.sync.aligned.m8n8.x4.shared.b16 {%0,%1,%2,%3}, [%4];"
                        : "=r"(t0), "=r"(t1), "=r"(t2), "=r"(t3) : "r"(addr));
                    b[nxt][nb * 2][0] = t0; b[nxt][nb * 2][1] = t2;
                    b[nxt][nb * 2 + 1][0] = t1; b[nxt][nb * 2 + 1][1] = t3;
                }
            }
            #pragma unroll
            for (int mi = 0; mi < 4; mi++)
                #pragma unroll
                for (int ni = 0; ni < 8; ni++) {
                    asm volatile(
                        "mma.sync.aligned.m16n8k16.row.col.f32.bf16.bf16.f32 "
                        "{%0,%1,%2,%3}, {%4,%5,%6,%7}, {%8,%9}, {%0,%1,%2,%3};"
                        : "+f"(acc[mi][ni][0]), "+f"(acc[mi][ni][1]),
                          "+f"(acc[mi][ni][2]), "+f"(acc[mi][ni][3])
                        : "r"(a[cur][mi][0]), "r"(a[cur][mi][1]),
                          "r"(a[cur][mi][2]), "r"(a[cur][mi][3]),
                          "r"(b[cur][ni][0]), "r"(b[cur][ni][1]));
                }
        }
    }

    const int rbase = m0 + wm * 64 + (lane >> 2);
    if (mode) {
        const int cbase = n0 + wn * 64 + (lane & 3) * 2;
        #pragma unroll
        for (int mi = 0; mi < 4; mi++)
            #pragma unroll
            for (int ni = 0; ni < 8; ni++) {
                int rr = rbase + mi * 16;
                int cc = cbase + ni * 8;
                size_t i0 = (size_t)rr * D_ + cc;
                size_t i1 = (size_t)(rr + 8) * D_ + cc;
                float2 x0 = *(const float2*)(addX + i0);
                float2 x1 = *(const float2*)(addX + i1);
                *(float2*)(Cout + i0) = make_float2(acc[mi][ni][0] + x0.x, acc[mi][ni][1] + x0.y);
                *(float2*)(Cout + i1) = make_float2(acc[mi][ni][2] + x1.x, acc[mi][ni][3] + x1.y);
            }
    } else {
        const int region = n0 >> 10;           // 0=Q, 1=K, 2=V
        const int cbase  = (n0 & 1023) + wn * 64 + (lane & 3) * 2;
        __nv_bfloat16* Cb = (region == 0) ? g_Qb : (region == 1) ? g_Kb : g_Vb;
        if (region < 2) {
            float* np = region ? g_npK : g_npQ;
            const int widx = ((n0 >> 8) & 3) * 4 + wn;     // 0..15 stripe index
            #pragma unroll
            for (int mi = 0; mi < 4; mi++) {
                float s0 = 0.f, s1 = 0.f;
                #pragma unroll
                for (int ni = 0; ni < 8; ni++) {
                    int rr = rbase + mi * 16;
                    int cc = cbase + ni * 8;
                    *(__nv_bfloat162*)(Cb + (size_t)rr * D_ + cc) =
                        __floats2bfloat162_rn(acc[mi][ni][0], acc[mi][ni][1]);
                    *(__nv_bfloat162*)(Cb + (size_t)(rr + 8) * D_ + cc) =
                        __floats2bfloat162_rn(acc[mi][ni][2], acc[mi][ni][3]);
                    s0 += acc[mi][ni][0] * acc[mi][ni][0] + acc[mi][ni][1] * acc[mi][ni][1];
                    s1 += acc[mi][ni][2] * acc[mi][ni][2] + acc[mi][ni][3] * acc[mi][ni][3];
                }
                s0 += __shfl_xor_sync(0xffffffffu, s0, 1);
                s0 += __shfl_xor_sync(0xffffffffu, s0, 2);
                s1 += __shfl_xor_sync(0xffffffffu, s1, 1);
                s1 += __shfl_xor_sync(0xffffffffu, s1, 2);
                if ((lane & 3) == 0) {
                    int rr = rbase + mi * 16;
                    np[(size_t)rr * 16 + widx]       = s0;
                    np[(size_t)(rr + 8) * 16 + widx] = s1;
                }
            }
        } else {
            #pragma unroll
            for (int mi = 0; mi < 4; mi++)
                #pragma unroll
                for (int ni = 0; ni < 8; ni++) {
                    int rr = rbase + mi * 16;
                    int cc = cbase + ni * 8;
                    *(__nv_bfloat162*)(Cb + (size_t)rr * D_ + cc) =
                        __floats2bfloat162_rn(acc[mi][ni][0], acc[mi][ni][1]);
                    *(__nv_bfloat162*)(Cb + (size_t)(rr + 8) * D_ + cc) =
                        __floats2bfloat162_rn(acc[mi][ni][2], acc[mi][ni][3]);
                }
        }
    }
}

// ---------------- rotary + scale + A partials : single pass, sincos recurrence ----------------
// Angles are linear in row position: anchor sincos once per pair per warp-row-group,
// then advance by a 4-FMA complex rotation per row (16 sincosf/thread vs 64).
// Block 256 (8 warps); each warp owns 8 consecutive rows. Grid = NROWS/64.
__global__ void __launch_bounds__(256) k_rowproc()
{
    const int w     = threadIdx.x >> 5;
    const int lane  = threadIdx.x & 31;
    const int gwarp = blockIdx.x * 8 + w;     // 0..4095
    const int row0  = gwarp * 8;

    float invf0[4], invf1[4];
    {
        double b0 = pow(10000.0, -(double)(2 * lane) * (1.0 / 256.0));
        double b1 = pow(10000.0, -(double)(2 * lane + 1) * (1.0 / 256.0));
        double f = 1.0;
        #pragma unroll
        for (int k = 0; k < 4; k++) {
            invf0[k] = (float)(b0 * f);
            invf1[k] = (float)(b1 * f);
            f *= 0.1;
        }
    }

    // anchor + step sincos per pair
    float c0[4], s0[4], c1[4], s1[4];      // current
    float cf0[4], sf0[4], cf1[4], sf1[4];  // per-row step
    {
        const float sbase = (float)(row0 & 8191);
        #pragma unroll
        for (int k = 0; k < 4; k++) {
            sincosf(sbase * invf0[k], &s0[k], &c0[k]);
            sincosf(sbase * invf1[k], &s1[k], &c1[k]);
            sincosf(invf0[k], &sf0[k], &cf0[k]);
            sincosf(invf1[k], &sf1[k], &cf1[k]);
        }
    }

    float accA[8][4];
    #pragma unroll
    for (int k = 0; k < 8; k++)
        #pragma unroll
        for (int e = 0; e < 4; e++) accA[k][e] = 0.f;

    const int c0i = 4 * lane;

    for (int r8 = 0; r8 < 8; r8++) {
        const int row = row0 + r8;
        const size_t base = (size_t)row * D_ + c0i;

        // norms from partials (broadcast loads, fixed order)
        float qs = 0.f, ks = 0.f;
        {
            const float4* npq = (const float4*)(g_npQ + (size_t)row * 16);
            const float4* npk = (const float4*)(g_npK + (size_t)row * 16);
            #pragma unroll
            for (int i = 0; i < 4; i++) {
                float4 tq = npq[i];
                float4 tk = npk[i];
                qs += tq.x + tq.y + tq.z + tq.w;
                ks += tk.x + tk.y + tk.z + tk.w;
            }
        }
        const float qi = rsqrtf(qs + 1e-6f);
        const float ki = rsqrtf(ks + 1e-6f);

        #pragma unroll
        for (int k = 0; k < 8; k++) {
            const __nv_bfloat162* qp = (const __nv_bfloat162*)(g_Qb + base + 128 * k);
            const __nv_bfloat162* kp = (const __nv_bfloat162*)(g_Kb + base + 128 * k);
            const __nv_bfloat162* vp = (const __nv_bfloat162*)(g_Vb + base + 128 * k);
            float2 qa = __bfloat1622float2(qp[0]);
            float2 qb = __bfloat1622float2(qp[1]);
            float2 ka = __bfloat1622float2(kp[0]);
            float2 kb = __bfloat1622float2(kp[1]);
            float2 va = __bfloat1622float2(vp[0]);
            float2 vb = __bfloat1622float2(vp[1]);
            if (k < 4) {
                const float cs0 = c0[k], sn0 = s0[k], cs1 = c1[k], sn1 = s1[k];
                float a, bb;
                a = qa.x * cs0 - qa.y * sn0; bb = qa.y * cs0 + qa.x * sn0; qa.x = a; qa.y = bb;
                a = qb.x * cs1 - qb.y * sn1; bb = qb.y * cs1 + qb.x * sn1; qb.x = a; qb.y = bb;
                a = ka.x * cs0 - ka.y * sn0; bb = ka.y * cs0 + ka.x * sn0; ka.x = a; ka.y = bb;
                a = kb.x * cs1 - kb.y * sn1; bb = kb.y * cs1 + kb.x * sn1; kb.x = a; kb.y = bb;
            }
            accA[k][0] += ka.x * ki * va.x;
            accA[k][1] += ka.y * ki * va.y;
            accA[k][2] += kb.x * ki * vb.x;
            accA[k][3] += kb.y * ki * vb.y;
            __nv_bfloat16* yp = g_Y + base + 128 * k;
            *(__nv_bfloat162*)(yp)     = __floats2bfloat162_rn(qa.x * qi, qa.y * qi);
            *(__nv_bfloat162*)(yp + 2) = __floats2bfloat162_rn(qb.x * qi, qb.y * qi);
        }

        // advance recurrence: theta += invf
        #pragma unroll
        for (int k = 0; k < 4; k++) {
            float nc0 = c0[k] * cf0[k] - s0[k] * sf0[k];
            float ns0 = s0[k] * cf0[k] + c0[k] * sf0[k];
            c0[k] = nc0; s0[k] = ns0;
            float nc1 = c1[k] * cf1[k] - s1[k] * sf1[k];
            float ns1 = s1[k] * cf1[k] + c1[k] * sf1[k];
            c1[k] = nc1; s1[k] = ns1;
        }
    }

    const size_t ap = (size_t)gwarp * D_ + c0i;
    #pragma unroll
    for (int k = 0; k < 8; k++)
        *(float4*)&g_Apart[ap + 128 * k] =
            make_float4(accA[k][0], accA[k][1], accA[k][2], accA[k][3]);
}

// ---------------- reduce A partials (stage 1: 4096 groups -> 8x per (b,d)) ----------------
__global__ void k_reduceA()
{
    int idx = blockIdx.x * blockDim.x + threadIdx.x;   // 0..32767
    int sub = idx >> 12;       // 0..7
    int rem = idx & 4095;      // b*1024 + d
    int b   = rem >> 10;
    int d   = rem & 1023;
    int g0  = b * 1024 + sub * 128;
    const float* p = g_Apart + (size_t)g0 * D_ + d;
    float s = 0.f;
    #pragma unroll 8
    for (int g = 0; g < 128; g++) s += p[(size_t)g * D_];
    g_A8[sub * 4096 + rem] = s;
}

// ---------------- W'_b = A_b (*) W_out  -> bf16, 4 copies (folds stage-2 reduce) ------------
__global__ void __launch_bounds__(256) k_scaleW(const float* __restrict__ Wout)
{
    int i4 = (blockIdx.x * blockDim.x + threadIdx.x) * 4;   // over D_*D_
    if (i4 >= D_ * D_) return;
    int d = i4 & 1023;
    float4 w = *(const float4*)(Wout + i4);
    #pragma unroll
    for (int b = 0; b < B_; b++) {
        float4 a = make_float4(0.f, 0.f, 0.f, 0.f);
        #pragma unroll
        for (int sub = 0; sub < 8; sub++) {
            float4 t = *(const float4*)(g_A8 + sub * 4096 + b * 1024 + d);
            a.x += t.x; a.y += t.y; a.z += t.z; a.w += t.w;
        }
        __nv_bfloat16* dst = g_Wpr + (size_t)b * D_ * D_ + i4;
        *(__nv_bfloat162*)(dst)     = __floats2bfloat162_rn(w.x * a.x, w.y * a.y);
        *(__nv_bfloat162*)(dst + 2) = __floats2bfloat162_rn(w.z * a.z, w.w * a.w);
    }
}

// ---------------- launch ----------------
extern "C" void kernel_launch(void* const* d_in, const int* in_sizes, int n_in,
                              void* d_out, int out_size)
{
    const float* X    = (const float*)d_in[0];
    const float* Win  = (const float*)d_in[1];
    const float* Wout = (const float*)d_in[2];
    const float* lg   = (const float*)d_in[3];
    const float* lb   = (const float*)d_in[4];
    float* out = (float*)d_out;

    cudaFuncSetAttribute(k_gemm, cudaFuncAttributeMaxDynamicSharedMemorySize, GEMM_SMEM);

    k_convert<<<(E3 * D_) / 4 / 256, 256>>>(Win, E3 * D_);
    k_layernorm<<<NROWS / 8, 256>>>(X, lg, lb);
    k_gemm<<<dim3(E3 / 256, NROWS / 128), 256, GEMM_SMEM>>>(nullptr, nullptr, 0);
    k_rowproc<<<NROWS / 64, 256>>>();
    k_reduceA<<<128, 256>>>();
    k_scaleW<<<D_ * D_ / 4 / 256, 256>>>(Wout);
    k_gemm<<<dim3(D_ / 256, NROWS / 128), 256, GEMM_SMEM>>>(X, out, 1);
}

// round 10
// speedup vs baseline: 1.0745x; 1.0745x over previous
#include <cuda_runtime.h>
#include <cuda_bf16.h>
#include <math.h>
#include <stdint.h>

#define D_      1024
#define S_      8192
#define B_      4
#define NROWS   (B_ * S_)      // 32768
#define E3      (3 * D_)       // 3072

// ---------------- scratch (static __device__: allocation-free) ----------------
__device__ __nv_bfloat16 g_Xn  [(size_t)NROWS * D_];   // 64 MiB
__device__ __nv_bfloat16 g_Win [(size_t)E3 * D_];      // 6 MiB
__device__ __nv_bfloat16 g_Wpr [(size_t)B_ * D_ * D_]; // 8 MiB  (A-scaled W_out, per batch)
__device__ __nv_bfloat16 g_Qb  [(size_t)NROWS * D_];   // 64 MiB
__device__ __nv_bfloat16 g_Kb  [(size_t)NROWS * D_];   // 64 MiB
__device__ __nv_bfloat16 g_Vb  [(size_t)NROWS * D_];   // 64 MiB
__device__ float         g_npQ [(size_t)NROWS * 16];   // 2 MiB  (per-row sq-norm partials)
__device__ float         g_npK [(size_t)NROWS * 16];   // 2 MiB
__device__ float2        g_rn  [(size_t)NROWS];        // 256 KiB (qi, ki per row)
__device__ float2        g_rot [(size_t)S_ * 256];     // 16 MiB  (cos,sin per (s, pair))
__device__ float         g_Apart[(size_t)4096 * D_];   // 16 MiB (per-8-row-group partials)
__device__ float         g_A8  [8 * B_ * D_];
__device__ __nv_bfloat16 g_Y   [(size_t)NROWS * D_];   // 64 MiB (Qhat, bf16)

__device__ __forceinline__ uint32_t smem_u32(const void* p) {
    uint32_t a;
    asm("{ .reg .u64 t; cvta.to.shared.u64 t, %1; cvt.u32.u64 %0, t; }" : "=r"(a) : "l"(p));
    return a;
}

// ---------------- fp32 -> bf16 weight conversion (W_in) ----------------
__global__ void k_convert(const float* __restrict__ src, int n)
{
    int i = (blockIdx.x * blockDim.x + threadIdx.x) * 4;
    if (i >= n) return;
    float4 v = *(const float4*)(src + i);
    *(__nv_bfloat162*)(g_Win + i)     = __floats2bfloat162_rn(v.x, v.y);
    *(__nv_bfloat162*)(g_Win + i + 2) = __floats2bfloat162_rn(v.z, v.w);
}

// ---------------- rotary cos/sin table: anchor + 64-step recurrence ----------------
// g_rot[s][p] = (cos(s*invf(p)), sin(s*invf(p))), invf(p) = 10000^(-p/256), p<256.
__global__ void k_rotfill()
{
    int id = blockIdx.x * blockDim.x + threadIdx.x;   // 0..32767
    int p  = id & 255;
    int sg = id >> 8;          // 0..127
    int s0 = sg * 64;
    double invf = pow(10000.0, -(double)p * (1.0 / 256.0));
    double th0  = fmod((double)s0 * invf, 6.283185307179586476925286766559);
    float c, s, cf, sf;
    sincosf((float)th0, &s, &c);
    sincosf((float)invf, &sf, &cf);
    float2* dst = g_rot + (size_t)s0 * 256 + p;
    #pragma unroll 8
    for (int j = 0; j < 64; j++) {
        *dst = make_float2(c, s);
        dst += 256;
        float nc = c * cf - s * sf;
        float ns = s * cf + c * sf;
        c = nc; s = ns;
    }
}

// ---------------- per-row inverse norms from GEMM1 partials ----------------
__global__ void k_rownorm()
{
    int row = blockIdx.x * blockDim.x + threadIdx.x;   // 0..NROWS-1
    const float4* npq = (const float4*)(g_npQ + (size_t)row * 16);
    const float4* npk = (const float4*)(g_npK + (size_t)row * 16);
    float qs = 0.f, ks = 0.f;
    #pragma unroll
    for (int i = 0; i < 4; i++) {
        float4 tq = npq[i];
        float4 tk = npk[i];
        qs += tq.x + tq.y + tq.z + tq.w;
        ks += tk.x + tk.y + tk.z + tk.w;
    }
    g_rn[row] = make_float2(rsqrtf(qs + 1e-6f), rsqrtf(ks + 1e-6f));
}

// ---------------- mma.sync bf16 GEMM ----------------
// 128x256 block tile, 8 warps (2m x 4n), warp tile 64x64, KC=64, 4-stage cp.async.
// mode 0: A=g_Xn, B=g_Win; C -> g_Qb/g_Kb/g_Vb (bf16; Q/K also write norm partials)
// mode 1: A=g_Y,  B=g_Wpr[batch]; C -> out (fp32, += X)
#define KC 64
#define NCHUNK 16
#define ASTAGE 16384
#define BSTAGE 32768
#define STAGE_BYTES (ASTAGE + BSTAGE)     // 48 KB
#define GEMM_SMEM (4 * STAGE_BYTES)       // 192 KB

__global__ void __launch_bounds__(256, 1) k_gemm(
    const float* __restrict__ addX, float* __restrict__ Cout, int mode)
{
    extern __shared__ char smem[];
    const int K = 1024;
    const int tid  = threadIdx.x;
    const int w    = tid >> 5;
    const int lane = tid & 31;
    const int wm   = w & 1;
    const int wn   = w >> 1;
    const int m0 = blockIdx.y * 128;
    const int n0 = blockIdx.x * 256;

    const __nv_bfloat16* Ag = mode ? g_Y : g_Xn;
    const __nv_bfloat16* Bg = mode ? (g_Wpr + (size_t)(m0 >> 13) * D_ * D_) : g_Win;

    const uint32_t sbase = smem_u32(smem);

    auto issue = [&](int kt) {
        const uint32_t st = sbase + (kt & 3) * STAGE_BYTES;
        #pragma unroll
        for (int i = 0; i < 12; i++) {
            int vec = i * 256 + tid;
            int isB = vec >= 1024;
            int vv  = isB ? vec - 1024 : vec;
            int row = vv >> 3;
            int c   = vv & 7;
            const __nv_bfloat16* src =
                (isB ? Bg + (size_t)(n0 + row) * K : Ag + (size_t)(m0 + row) * K)
                + kt * KC + c * 8;
            uint32_t dst = st + (isB ? ASTAGE : 0) + row * 128 + (((c ^ (row & 7)) << 4));
            asm volatile("cp.async.cg.shared.global [%0], [%1], 16;" :: "r"(dst), "l"(src));
        }
        asm volatile("cp.async.commit_group;" ::: "memory");
    };

    float acc[4][8][4];
    #pragma unroll
    for (int mi = 0; mi < 4; mi++)
        #pragma unroll
        for (int ni = 0; ni < 8; ni++)
            #pragma unroll
            for (int e = 0; e < 4; e++) acc[mi][ni][e] = 0.f;

    issue(0); issue(1); issue(2);

    const int lr = lane & 15;
    const int lc = lane >> 4;

    uint32_t a[2][4][4], b[2][8][2];

    for (int kt = 0; kt < NCHUNK; kt++) {
        asm volatile("cp.async.wait_group 2;" ::: "memory");
        __syncthreads();
        if (kt + 3 < NCHUNK) issue(kt + 3);
        else asm volatile("cp.async.commit_group;" ::: "memory");

        const uint32_t sA = sbase + (kt & 3) * STAGE_BYTES;
        const uint32_t sB = sA + ASTAGE;

        {
            const int c = lc;
            #pragma unroll
            for (int mi = 0; mi < 4; mi++) {
                int r = wm * 64 + mi * 16 + lr;
                uint32_t addr = sA + r * 128 + ((c ^ (r & 7)) << 4);
                asm volatile("ldmatrix.sync.aligned.m8n8.x4.shared.b16 {%0,%1,%2,%3}, [%4];"
                    : "=r"(a[0][mi][0]), "=r"(a[0][mi][1]), "=r"(a[0][mi][2]), "=r"(a[0][mi][3])
                    : "r"(addr));
            }
            #pragma unroll
            for (int nb = 0; nb < 4; nb++) {
                int r = wn * 64 + nb * 16 + lr;
                uint32_t addr = sB + r * 128 + ((c ^ (r & 7)) << 4);
                uint32_t t0, t1, t2, t3;
                asm volatile("ldmatrix.sync.aligned.m8n8.x4.shared.b16 {%0,%1,%2,%3}, [%4];"
                    : "=r"(t0), "=r"(t1), "=r"(t2), "=r"(t3) : "r"(addr));
                b[0][nb * 2][0] = t0; b[0][nb * 2][1] = t2;
                b[0][nb * 2 + 1][0] = t1; b[0][nb * 2 + 1][1] = t3;
            }
        }

        #pragma unroll
        for (int ks = 0; ks < 4; ks++) {
            const int cur = ks & 1;
            const int nxt = cur ^ 1;
            if (ks < 3) {
                const int c = (ks + 1) * 2 + lc;
                #pragma unroll
                for (int mi = 0; mi < 4; mi++) {
                    int r = wm * 64 + mi * 16 + lr;
                    uint32_t addr = sA + r * 128 + ((c ^ (r & 7)) << 4);
                    asm volatile("ldmatrix.sync.aligned.m8n8.x4.shared.b16 {%0,%1,%2,%3}, [%4];"
                        : "=r"(a[nxt][mi][0]), "=r"(a[nxt][mi][1]),
                          "=r"(a[nxt][mi][2]), "=r"(a[nxt][mi][3]) : "r"(addr));
                }
                #pragma unroll
                for (int nb = 0; nb < 4; nb++) {
                    int r = wn * 64 + nb * 16 + lr;
                    uint32_t addr = sB + r * 128 + ((c ^ (r & 7)) << 4);
                    uint32_t t0, t1, t2, t3;
                    asm volatile("ldmatrix.sync.aligned.m8n8.x4.shared.b16 {%0,%1,%2,%3}, [%4];"
                        : "=r"(t0), "=r"(t1), "=r"(t2), "=r"(t3) : "r"(addr));
                    b[nxt][nb * 2][0] = t0; b[nxt][nb * 2][1] = t2;
                    b[nxt][nb * 2 + 1][0] = t1; b[nxt][nb * 2 + 1][1] = t3;
                }
            }
            #pragma unroll
            for (int mi = 0; mi < 4; mi++)
                #pragma unroll
                for (int ni = 0; ni < 8; ni++) {
                    asm volatile(
                        "mma.sync.aligned.m16n8k16.row.col.f32.bf16.bf16.f32 "
                        "{%0,%1,%2,%3}, {%4,%5,%6,%7}, {%8,%9}, {%0,%1,%2,%3};"
                        : "+f"(acc[mi][ni][0]), "+f"(acc[mi][ni][1]),
                          "+f"(acc[mi][ni][2]), "+f"(acc[mi][ni][3])
                        : "r"(a[cur][mi][0]), "r"(a[cur][mi][1]),
                          "r"(a[cur][mi][2]), "r"(a[cur][mi][3]),
                          "r"(b[cur][ni][0]), "r"(b[cur][ni][1]));
                }
        }
    }

    const int rbase = m0 + wm * 64 + (lane >> 2);
    if (mode) {
        const int cbase = n0 + wn * 64 + (lane & 3) * 2;
        #pragma unroll
        for (int mi = 0; mi < 4; mi++)
            #pragma unroll
            for (int ni = 0; ni < 8; ni++) {
                int rr = rbase + mi * 16;
                int cc = cbase + ni * 8;
                size_t i0 = (size_t)rr * D_ + cc;
                size_t i1 = (size_t)(rr + 8) * D_ + cc;
                float2 x0 = *(const float2*)(addX + i0);
                float2 x1 = *(const float2*)(addX + i1);
                *(float2*)(Cout + i0) = make_float2(acc[mi][ni][0] + x0.x, acc[mi][ni][1] + x0.y);
                *(float2*)(Cout + i1) = make_float2(acc[mi][ni][2] + x1.x, acc[mi][ni][3] + x1.y);
            }
    } else {
        const int region = n0 >> 10;           // 0=Q, 1=K, 2=V
        const int cbase  = (n0 & 1023) + wn * 64 + (lane & 3) * 2;
        __nv_bfloat16* Cb = (region == 0) ? g_Qb : (region == 1) ? g_Kb : g_Vb;
        if (region < 2) {
            float* np = region ? g_npK : g_npQ;
            const int widx = ((n0 >> 8) & 3) * 4 + wn;     // 0..15 stripe index
            #pragma unroll
            for (int mi = 0; mi < 4; mi++) {
                float s0 = 0.f, s1 = 0.f;
                #pragma unroll
                for (int ni = 0; ni < 8; ni++) {
                    int rr = rbase + mi * 16;
                    int cc = cbase + ni * 8;
                    *(__nv_bfloat162*)(Cb + (size_t)rr * D_ + cc) =
                        __floats2bfloat162_rn(acc[mi][ni][0], acc[mi][ni][1]);
                    *(__nv_bfloat162*)(Cb + (size_t)(rr + 8) * D_ + cc) =
                        __floats2bfloat162_rn(acc[mi][ni][2], acc[mi][ni][3]);
                    s0 += acc[mi][ni][0] * acc[mi][ni][0] + acc[mi][ni][1] * acc[mi][ni][1];
                    s1 += acc[mi][ni][2] * acc[mi][ni][2] + acc[mi][ni][3] * acc[mi][ni][3];
                }
                s0 += __shfl_xor_sync(0xffffffffu, s0, 1);
                s0 += __shfl_xor_sync(0xffffffffu, s0, 2);
                s1 += __shfl_xor_sync(0xffffffffu, s1, 1);
                s1 += __shfl_xor_sync(0xffffffffu, s1, 2);
                if ((lane & 3) == 0) {
                    int rr = rbase + mi * 16;
                    np[(size_t)rr * 16 + widx]       = s0;
                    np[(size_t)(rr + 8) * 16 + widx] = s1;
                }
            }
        } else {
            #pragma unroll
            for (int mi = 0; mi < 4; mi++)
                #pragma unroll
                for (int ni = 0; ni < 8; ni++) {
                    int rr = rbase + mi * 16;
                    int cc = cbase + ni * 8;
                    *(__nv_bfloat162*)(Cb + (size_t)rr * D_ + cc) =
                        __floats2bfloat162_rn(acc[mi][ni][0], acc[mi][ni][1]);
                    *(__nv_bfloat162*)(Cb + (size_t)(rr + 8) * D_ + cc) =
                        __floats2bfloat162_rn(acc[mi][ni][2], acc[mi][ni][3]);
                }
        }
    }
}

// ---------------- rotary + scale + A partials : fully parallel streaming ----------------
// Thread owns 8 consecutive cols of one row; block = 2 rows x 8 row-iterations.
// No MUFU, no shuffles, no barriers; all per-row state from g_rot / g_rn tables.
// Grid = NROWS/16.
__global__ void __launch_bounds__(256) k_rowproc()
{
    const int tid = threadIdx.x;
    const int r2  = tid >> 7;            // 0..1
    const int c   = tid & 127;           // col block
    const int col = c * 8;
    const bool rot = (col < 512);
    const int rowbase = blockIdx.x * 16 + r2 * 8;

    float accA[8];
    #pragma unroll
    for (int j = 0; j < 8; j++) accA[j] = 0.f;

    #pragma unroll 2
    for (int it = 0; it < 8; it++) {
        const int row = rowbase + it;
        const size_t base = (size_t)row * D_ + col;
        const float2 rn = g_rn[row];                  // (qi, ki) broadcast

        uint4 qu = *(const uint4*)(g_Qb + base);
        uint4 ku = *(const uint4*)(g_Kb + base);
        uint4 vu = *(const uint4*)(g_Vb + base);

        float2 q[4], k[4], v[4];
        #pragma unroll
        for (int j = 0; j < 4; j++) {
            q[j] = __bfloat1622float2(((const __nv_bfloat162*)&qu)[j]);
            k[j] = __bfloat1622float2(((const __nv_bfloat162*)&ku)[j]);
            v[j] = __bfloat1622float2(((const __nv_bfloat162*)&vu)[j]);
        }

        if (rot) {
            const float4* rp = (const float4*)(g_rot + (size_t)(row & 8191) * 256 + (col >> 1));
            float4 r01 = rp[0];      // pair0 (cos,sin), pair1 (cos,sin)
            float4 r23 = rp[1];      // pair2, pair3
            float cs[4] = { r01.x, r01.z, r23.x, r23.z };
            float sn[4] = { r01.y, r01.w, r23.y, r23.w };
            #pragma unroll
            for (int j = 0; j < 4; j++) {
                float a, bb;
                a = q[j].x * cs[j] - q[j].y * sn[j];
                bb = q[j].y * cs[j] + q[j].x * sn[j];
                q[j].x = a; q[j].y = bb;
                a = k[j].x * cs[j] - k[j].y * sn[j];
                bb = k[j].y * cs[j] + k[j].x * sn[j];
                k[j].x = a; k[j].y = bb;
            }
        }

        uint4 yo;
        #pragma unroll
        for (int j = 0; j < 4; j++) {
            accA[2 * j]     += k[j].x * rn.y * v[j].x;
            accA[2 * j + 1] += k[j].y * rn.y * v[j].y;
            ((__nv_bfloat162*)&yo)[j] = __floats2bfloat162_rn(q[j].x * rn.x, q[j].y * rn.x);
        }
        *(uint4*)(g_Y + base) = yo;
    }

    float* ap = g_Apart + (size_t)(blockIdx.x * 2 + r2) * D_ + col;
    *(float4*)(ap)     = make_float4(accA[0], accA[1], accA[2], accA[3]);
    *(float4*)(ap + 4) = make_float4(accA[4], accA[5], accA[6], accA[7]);
}

// ---------------- reduce A partials (stage 1: 4096 groups -> 8x per (b,d)) ----------------
__global__ void k_reduceA()
{
    int idx = blockIdx.x * blockDim.x + threadIdx.x;   // 0..32767
    int sub = idx >> 12;       // 0..7
    int rem = idx & 4095;      // b*1024 + d
    int b   = rem >> 10;
    int d   = rem & 1023;
    int g0  = b * 1024 + sub * 128;
    const float* p = g_Apart + (size_t)g0 * D_ + d;
    float s = 0.f;
    #pragma unroll 8
    for (int g = 0; g < 128; g++) s += p[(size_t)g * D_];
    g_A8[sub * 4096 + rem] = s;
}

// ---------------- W'_b = A_b (*) W_out  -> bf16, 4 copies (folds stage-2 reduce) ------------
__global__ void __launch_bounds__(256) k_scaleW(const float* __restrict__ Wout)
{
    int i4 = (blockIdx.x * blockDim.x + threadIdx.x) * 4;   // over D_*D_
    if (i4 >= D_ * D_) return;
    int d = i4 & 1023;
    float4 w = *(const float4*)(Wout + i4);
    #pragma unroll
    for (int b = 0; b < B_; b++) {
        float4 a = make_float4(0.f, 0.f, 0.f, 0.f);
        #pragma unroll
        for (int sub = 0; sub < 8; sub++) {
            float4 t = *(const float4*)(g_A8 + sub * 4096 + b * 1024 + d);
            a.x += t.x; a.y += t.y; a.z += t.z; a.w += t.w;
        }
        __nv_bfloat16* dst = g_Wpr + (size_t)b * D_ * D_ + i4;
        *(__nv_bfloat162*)(dst)     = __floats2bfloat162_rn(w.x * a.x, w.y * a.y);
        *(__nv_bfloat162*)(dst + 2) = __floats2bfloat162_rn(w.z * a.z, w.w * a.w);
    }
}

// ---------------- LayerNorm: warp-per-row, no barriers ----------------
__global__ void __launch_bounds__(256) k_layernorm(
    const float* __restrict__ X, const float* __restrict__ lg, const float* __restrict__ lb)
{
    const int w    = threadIdx.x >> 5;
    const int lane = threadIdx.x & 31;
    const int row  = blockIdx.x * 8 + w;
    const int c0   = 4 * lane;
    const float* xp = X + (size_t)row * D_ + c0;

    float x[8][4];
    float s = 0.f, sq = 0.f;
    #pragma unroll
    for (int k = 0; k < 8; k++) {
        float4 v = *(const float4*)(xp + 128 * k);
        x[k][0] = v.x; x[k][1] = v.y; x[k][2] = v.z; x[k][3] = v.w;
        s  += v.x + v.y + v.z + v.w;
        sq += v.x * v.x + v.y * v.y + v.z * v.z + v.w * v.w;
    }
    #pragma unroll
    for (int o = 16; o; o >>= 1) {
        s  += __shfl_xor_sync(0xffffffffu, s, o);
        sq += __shfl_xor_sync(0xffffffffu, sq, o);
    }
    const float mu  = s * (1.f / D_);
    const float var = sq * (1.f / D_) - mu * mu;
    const float rs  = rsqrtf(var + 1e-5f);

    __nv_bfloat16* op = g_Xn + (size_t)row * D_ + c0;
    #pragma unroll
    for (int k = 0; k < 8; k++) {
        float4 g4 = *(const float4*)(lg + c0 + 128 * k);
        float4 b4 = *(const float4*)(lb + c0 + 128 * k);
        float y0 = (x[k][0] - mu) * rs * g4.x + b4.x;
        float y1 = (x[k][1] - mu) * rs * g4.y + b4.y;
        float y2 = (x[k][2] - mu) * rs * g4.z + b4.z;
        float y3 = (x[k][3] - mu) * rs * g4.w + b4.w;
        *(__nv_bfloat162*)(op + 128 * k)     = __floats2bfloat162_rn(y0, y1);
        *(__nv_bfloat162*)(op + 128 * k + 2) = __floats2bfloat162_rn(y2, y3);
    }
}

// ---------------- launch ----------------
extern "C" void kernel_launch(void* const* d_in, const int* in_sizes, int n_in,
                              void* d_out, int out_size)
{
    const float* X    = (const float*)d_in[0];
    const float* Win  = (const float*)d_in[1];
    const float* Wout = (const float*)d_in[2];
    const float* lg   = (const float*)d_in[3];
    const float* lb   = (const float*)d_in[4];
    float* out = (float*)d_out;

    cudaFuncSetAttribute(k_gemm, cudaFuncAttributeMaxDynamicSharedMemorySize, GEMM_SMEM);

    k_convert<<<(E3 * D_) / 4 / 256, 256>>>(Win, E3 * D_);
    k_rotfill<<<128, 256>>>();
    k_layernorm<<<NROWS / 8, 256>>>(X, lg, lb);
    k_gemm<<<dim3(E3 / 256, NROWS / 128), 256, GEMM_SMEM>>>(nullptr, nullptr, 0);
    k_rownorm<<<NROWS / 256, 256>>>();
    k_rowproc<<<NROWS / 16, 256>>>();
    k_reduceA<<<128, 256>>>();
    k_scaleW<<<D_ * D_ / 4 / 256, 256>>>(Wout);
    k_gemm<<<dim3(D_ / 256, NROWS / 128), 256, GEMM_SMEM>>>(X, out, 1);
}

// round 11
// speedup vs baseline: 1.0956x; 1.0196x over previous
#include <cuda_runtime.h>
#include <cuda_bf16.h>
#include <math.h>
#include <stdint.h>

#define D_      1024
#define S_      8192
#define B_      4
#define NROWS   (B_ * S_)      // 32768
#define E3      (3 * D_)       // 3072

// ---------------- scratch (static __device__: allocation-free) ----------------
__device__ __nv_bfloat16 g_Xn  [(size_t)NROWS * D_];   // 64 MiB
__device__ __nv_bfloat16 g_Win [(size_t)E3 * D_];      // 6 MiB
__device__ __nv_bfloat16 g_Wpr [(size_t)B_ * D_ * D_]; // 8 MiB  (A-scaled W_out, per batch)
__device__ __nv_bfloat16 g_Qb  [(size_t)NROWS * D_];   // 64 MiB
__device__ __nv_bfloat16 g_Kb  [(size_t)NROWS * D_];   // 64 MiB
__device__ __nv_bfloat16 g_Vb  [(size_t)NROWS * D_];   // 64 MiB
__device__ float         g_npQ [(size_t)NROWS * 16];   // 2 MiB  (per-row sq-norm partials)
__device__ float         g_npK [(size_t)NROWS * 16];   // 2 MiB
__device__ float2        g_rn  [(size_t)NROWS];        // 256 KiB (qi, ki per row)
__device__ float2        g_rot [(size_t)S_ * 256];     // 16 MiB  (cos,sin per (s, pair))
__device__ float         g_Apart[(size_t)4096 * D_];   // 16 MiB (per-8-row-group partials)
__device__ float         g_A8  [8 * B_ * D_];
__device__ __nv_bfloat16 g_Y   [(size_t)NROWS * D_];   // 64 MiB (Qhat, bf16)

__device__ __forceinline__ uint32_t smem_u32(const void* p) {
    uint32_t a;
    asm("{ .reg .u64 t; cvta.to.shared.u64 t, %1; cvt.u32.u64 %0, t; }" : "=r"(a) : "l"(p));
    return a;
}

// ---------------- fp32 -> bf16 weight conversion (W_in) ----------------
__global__ void k_convert(const float* __restrict__ src, int n)
{
    int i = (blockIdx.x * blockDim.x + threadIdx.x) * 4;
    if (i >= n) return;
    float4 v = *(const float4*)(src + i);
    *(__nv_bfloat162*)(g_Win + i)     = __floats2bfloat162_rn(v.x, v.y);
    *(__nv_bfloat162*)(g_Win + i + 2) = __floats2bfloat162_rn(v.z, v.w);
}

// ---------------- rotary cos/sin table: anchor + 64-step recurrence ----------------
__global__ void k_rotfill()
{
    int id = blockIdx.x * blockDim.x + threadIdx.x;   // 0..32767
    int p  = id & 255;
    int sg = id >> 8;          // 0..127
    int s0 = sg * 64;
    double invf = pow(10000.0, -(double)p * (1.0 / 256.0));
    double th0  = fmod((double)s0 * invf, 6.283185307179586476925286766559);
    float c, s, cf, sf;
    sincosf((float)th0, &s, &c);
    sincosf((float)invf, &sf, &cf);
    float2* dst = g_rot + (size_t)s0 * 256 + p;
    #pragma unroll 8
    for (int j = 0; j < 64; j++) {
        *dst = make_float2(c, s);
        dst += 256;
        float nc = c * cf - s * sf;
        float ns = s * cf + c * sf;
        c = nc; s = ns;
    }
}

// ---------------- per-row inverse norms from GEMM1 partials ----------------
__global__ void k_rownorm()
{
    int row = blockIdx.x * blockDim.x + threadIdx.x;   // 0..NROWS-1
    const float4* npq = (const float4*)(g_npQ + (size_t)row * 16);
    const float4* npk = (const float4*)(g_npK + (size_t)row * 16);
    float qs = 0.f, ks = 0.f;
    #pragma unroll
    for (int i = 0; i < 4; i++) {
        float4 tq = npq[i];
        float4 tk = npk[i];
        qs += tq.x + tq.y + tq.z + tq.w;
        ks += tk.x + tk.y + tk.z + tk.w;
    }
    g_rn[row] = make_float2(rsqrtf(qs + 1e-6f), rsqrtf(ks + 1e-6f));
}

// ---------------- mma.sync bf16 GEMM ----------------
// 128x256 block tile, 8 warps (2m x 4n), warp tile 64x64, KC=64, 4-stage cp.async.
// cp.async issues are distributed across the ks pipeline (3 per step) to keep
// the tensor pipe fed across chunk boundaries.
#define KC 64
#define NCHUNK 16
#define ASTAGE 16384
#define BSTAGE 32768
#define STAGE_BYTES (ASTAGE + BSTAGE)     // 48 KB
#define GEMM_SMEM (4 * STAGE_BYTES)       // 192 KB

__global__ void __launch_bounds__(256, 1) k_gemm(
    const float* __restrict__ addX, float* __restrict__ Cout, int mode)
{
    extern __shared__ char smem[];
    const int K = 1024;
    const int tid  = threadIdx.x;
    const int w    = tid >> 5;
    const int lane = tid & 31;
    const int wm   = w & 1;
    const int wn   = w >> 1;
    const int m0 = blockIdx.y * 128;
    const int n0 = blockIdx.x * 256;

    const __nv_bfloat16* Ag = mode ? g_Y : g_Xn;
    const __nv_bfloat16* Bg = mode ? (g_Wpr + (size_t)(m0 >> 13) * D_ * D_) : g_Win;

    const uint32_t sbase = smem_u32(smem);

    // one 3-cp.async piece of a chunk's 12 copies
    auto issue_piece = [&](int kt, int p) {
        const uint32_t st = sbase + (kt & 3) * STAGE_BYTES;
        #pragma unroll
        for (int i = 3 * p; i < 3 * p + 3; i++) {
            int vec = i * 256 + tid;
            int isB = vec >= 1024;
            int vv  = isB ? vec - 1024 : vec;
            int row = vv >> 3;
            int c   = vv & 7;
            const __nv_bfloat16* src =
                (isB ? Bg + (size_t)(n0 + row) * K : Ag + (size_t)(m0 + row) * K)
                + kt * KC + c * 8;
            uint32_t dst = st + (isB ? ASTAGE : 0) + row * 128 + (((c ^ (row & 7)) << 4));
            asm volatile("cp.async.cg.shared.global [%0], [%1], 16;" :: "r"(dst), "l"(src));
        }
    };
    auto issue_all = [&](int kt) {
        #pragma unroll
        for (int p = 0; p < 4; p++) issue_piece(kt, p);
        asm volatile("cp.async.commit_group;" ::: "memory");
    };

    float acc[4][8][4];
    #pragma unroll
    for (int mi = 0; mi < 4; mi++)
        #pragma unroll
        for (int ni = 0; ni < 8; ni++)
            #pragma unroll
            for (int e = 0; e < 4; e++) acc[mi][ni][e] = 0.f;

    issue_all(0); issue_all(1); issue_all(2);

    const int lr = lane & 15;
    const int lc = lane >> 4;

    uint32_t a[2][4][4], b[2][8][2];

    for (int kt = 0; kt < NCHUNK; kt++) {
        asm volatile("cp.async.wait_group 2;" ::: "memory");
        __syncthreads();

        const uint32_t sA = sbase + (kt & 3) * STAGE_BYTES;
        const uint32_t sB = sA + ASTAGE;
        const bool doIssue = (kt + 3 < NCHUNK);

        // ks=0 fragment loads first -> HMMAs resume ASAP
        {
            const int c = lc;
            #pragma unroll
            for (int mi = 0; mi < 4; mi++) {
                int r = wm * 64 + mi * 16 + lr;
                uint32_t addr = sA + r * 128 + ((c ^ (r & 7)) << 4);
                asm volatile("ldmatrix.sync.aligned.m8n8.x4.shared.b16 {%0,%1,%2,%3}, [%4];"
                    : "=r"(a[0][mi][0]), "=r"(a[0][mi][1]), "=r"(a[0][mi][2]), "=r"(a[0][mi][3])
                    : "r"(addr));
            }
            #pragma unroll
            for (int nb = 0; nb < 4; nb++) {
                int r = wn * 64 + nb * 16 + lr;
                uint32_t addr = sB + r * 128 + ((c ^ (r & 7)) << 4);
                uint32_t t0, t1, t2, t3;
                asm volatile("ldmatrix.sync.aligned.m8n8.x4.shared.b16 {%0,%1,%2,%3}, [%4];"
                    : "=r"(t0), "=r"(t1), "=r"(t2), "=r"(t3) : "r"(addr));
                b[0][nb * 2][0] = t0; b[0][nb * 2][1] = t2;
                b[0][nb * 2 + 1][0] = t1; b[0][nb * 2 + 1][1] = t3;
            }
        }

        #pragma unroll
        for (int ks = 0; ks < 4; ks++) {
            const int cur = ks & 1;
            const int nxt = cur ^ 1;
            if (ks < 3) {
                const int c = (ks + 1) * 2 + lc;
                #pragma unroll
                for (int mi = 0; mi < 4; mi++) {
                    int r = wm * 64 + mi * 16 + lr;
                    uint32_t addr = sA + r * 128 + ((c ^ (r & 7)) << 4);
                    asm volatile("ldmatrix.sync.aligned.m8n8.x4.shared.b16 {%0,%1,%2,%3}, [%4];"
                        : "=r"(a[nxt][mi][0]), "=r"(a[nxt][mi][1]),
                          "=r"(a[nxt][mi][2]), "=r"(a[nxt][mi][3]) : "r"(addr));
                }
                #pragma unroll
                for (int nb = 0; nb < 4; nb++) {
                    int r = wn * 64 + nb * 16 + lr;
                    uint32_t addr = sB + r * 128 + ((c ^ (r & 7)) << 4);
                    uint32_t t0, t1, t2, t3;
                    asm volatile("ldmatrix.sync.aligned.m8n8.x4.shared.b16 {%0,%1,%2,%3}, [%4];"
                        : "=r"(t0), "=r"(t1), "=r"(t2), "=r"(t3) : "r"(addr));
                    b[nxt][nb * 2][0] = t0; b[nxt][nb * 2][1] = t2;
                    b[nxt][nb * 2 + 1][0] = t1; b[nxt][nb * 2 + 1][1] = t3;
                }
            }
            // interleave 3 of the next stage's cp.asyncs here
            if (doIssue) issue_piece(kt + 3, ks);

            #pragma unroll
            for (int mi = 0; mi < 4; mi++)
                #pragma unroll
                for (int ni = 0; ni < 8; ni++) {
                    asm volatile(
                        "mma.sync.aligned.m16n8k16.row.col.f32.bf16.bf16.f32 "
                        "{%0,%1,%2,%3}, {%4,%5,%6,%7}, {%8,%9}, {%0,%1,%2,%3};"
                        : "+f"(acc[mi][ni][0]), "+f"(acc[mi][ni][1]),
                          "+f"(acc[mi][ni][2]), "+f"(acc[mi][ni][3])
                        : "r"(a[cur][mi][0]), "r"(a[cur][mi][1]),
                          "r"(a[cur][mi][2]), "r"(a[cur][mi][3]),
                          "r"(b[cur][ni][0]), "r"(b[cur][ni][1]));
                }
        }
        asm volatile("cp.async.commit_group;" ::: "memory");
    }

    const int rbase = m0 + wm * 64 + (lane >> 2);
    if (mode) {
        const int cbase = n0 + wn * 64 + (lane & 3) * 2;
        #pragma unroll
        for (int mi = 0; mi < 4; mi++)
            #pragma unroll
            for (int ni = 0; ni < 8; ni++) {
                int rr = rbase + mi * 16;
                int cc = cbase + ni * 8;
                size_t i0 = (size_t)rr * D_ + cc;
                size_t i1 = (size_t)(rr + 8) * D_ + cc;
                float2 x0 = *(const float2*)(addX + i0);
                float2 x1 = *(const float2*)(addX + i1);
                *(float2*)(Cout + i0) = make_float2(acc[mi][ni][0] + x0.x, acc[mi][ni][1] + x0.y);
                *(float2*)(Cout + i1) = make_float2(acc[mi][ni][2] + x1.x, acc[mi][ni][3] + x1.y);
            }
    } else {
        const int region = n0 >> 10;           // 0=Q, 1=K, 2=V
        const int cbase  = (n0 & 1023) + wn * 64 + (lane & 3) * 2;
        __nv_bfloat16* Cb = (region == 0) ? g_Qb : (region == 1) ? g_Kb : g_Vb;
        if (region < 2) {
            float* np = region ? g_npK : g_npQ;
            const int widx = ((n0 >> 8) & 3) * 4 + wn;     // 0..15 stripe index
            #pragma unroll
            for (int mi = 0; mi < 4; mi++) {
                float s0 = 0.f, s1 = 0.f;
                #pragma unroll
                for (int ni = 0; ni < 8; ni++) {
                    int rr = rbase + mi * 16;
                    int cc = cbase + ni * 8;
                    *(__nv_bfloat162*)(Cb + (size_t)rr * D_ + cc) =
                        __floats2bfloat162_rn(acc[mi][ni][0], acc[mi][ni][1]);
                    *(__nv_bfloat162*)(Cb + (size_t)(rr + 8) * D_ + cc) =
                        __floats2bfloat162_rn(acc[mi][ni][2], acc[mi][ni][3]);
                    s0 += acc[mi][ni][0] * acc[mi][ni][0] + acc[mi][ni][1] * acc[mi][ni][1];
                    s1 += acc[mi][ni][2] * acc[mi][ni][2] + acc[mi][ni][3] * acc[mi][ni][3];
                }
                s0 += __shfl_xor_sync(0xffffffffu, s0, 1);
                s0 += __shfl_xor_sync(0xffffffffu, s0, 2);
                s1 += __shfl_xor_sync(0xffffffffu, s1, 1);
                s1 += __shfl_xor_sync(0xffffffffu, s1, 2);
                if ((lane & 3) == 0) {
                    int rr = rbase + mi * 16;
                    np[(size_t)rr * 16 + widx]       = s0;
                    np[(size_t)(rr + 8) * 16 + widx] = s1;
                }
            }
        } else {
            #pragma unroll
            for (int mi = 0; mi < 4; mi++)
                #pragma unroll
                for (int ni = 0; ni < 8; ni++) {
                    int rr = rbase + mi * 16;
                    int cc = cbase + ni * 8;
                    *(__nv_bfloat162*)(Cb + (size_t)rr * D_ + cc) =
                        __floats2bfloat162_rn(acc[mi][ni][0], acc[mi][ni][1]);
                    *(__nv_bfloat162*)(Cb + (size_t)(rr + 8) * D_ + cc) =
                        __floats2bfloat162_rn(acc[mi][ni][2], acc[mi][ni][3]);
                }
        }
    }
}

// ---------------- rotary + scale + A partials : fully parallel streaming ----------------
__global__ void __launch_bounds__(256) k_rowproc()
{
    const int tid = threadIdx.x;
    const int r2  = tid >> 7;            // 0..1
    const int c   = tid & 127;           // col block
    const int col = c * 8;
    const bool rot = (col < 512);
    const int rowbase = blockIdx.x * 16 + r2 * 8;

    float accA[8];
    #pragma unroll
    for (int j = 0; j < 8; j++) accA[j] = 0.f;

    #pragma unroll 2
    for (int it = 0; it < 8; it++) {
        const int row = rowbase + it;
        const size_t base = (size_t)row * D_ + col;
        const float2 rn = g_rn[row];                  // (qi, ki) broadcast

        uint4 qu = *(const uint4*)(g_Qb + base);
        uint4 ku = *(const uint4*)(g_Kb + base);
        uint4 vu = *(const uint4*)(g_Vb + base);

        float2 q[4], k[4], v[4];
        #pragma unroll
        for (int j = 0; j < 4; j++) {
            q[j] = __bfloat1622float2(((const __nv_bfloat162*)&qu)[j]);
            k[j] = __bfloat1622float2(((const __nv_bfloat162*)&ku)[j]);
            v[j] = __bfloat1622float2(((const __nv_bfloat162*)&vu)[j]);
        }

        if (rot) {
            const float4* rp = (const float4*)(g_rot + (size_t)(row & 8191) * 256 + (col >> 1));
            float4 r01 = rp[0];
            float4 r23 = rp[1];
            float cs[4] = { r01.x, r01.z, r23.x, r23.z };
            float sn[4] = { r01.y, r01.w, r23.y, r23.w };
            #pragma unroll
            for (int j = 0; j < 4; j++) {
                float a, bb;
                a = q[j].x * cs[j] - q[j].y * sn[j];
                bb = q[j].y * cs[j] + q[j].x * sn[j];
                q[j].x = a; q[j].y = bb;
                a = k[j].x * cs[j] - k[j].y * sn[j];
                bb = k[j].y * cs[j] + k[j].x * sn[j];
                k[j].x = a; k[j].y = bb;
            }
        }

        uint4 yo;
        #pragma unroll
        for (int j = 0; j < 4; j++) {
            accA[2 * j]     += k[j].x * rn.y * v[j].x;
            accA[2 * j + 1] += k[j].y * rn.y * v[j].y;
            ((__nv_bfloat162*)&yo)[j] = __floats2bfloat162_rn(q[j].x * rn.x, q[j].y * rn.x);
        }
        *(uint4*)(g_Y + base) = yo;
    }

    float* ap = g_Apart + (size_t)(blockIdx.x * 2 + r2) * D_ + col;
    *(float4*)(ap)     = make_float4(accA[0], accA[1], accA[2], accA[3]);
    *(float4*)(ap + 4) = make_float4(accA[4], accA[5], accA[6], accA[7]);
}

// ---------------- reduce A partials (stage 1: 4096 groups -> 8x per (b,d)) ----------------
__global__ void k_reduceA()
{
    int idx = blockIdx.x * blockDim.x + threadIdx.x;   // 0..32767
    int sub = idx >> 12;       // 0..7
    int rem = idx & 4095;      // b*1024 + d
    int b   = rem >> 10;
    int d   = rem & 1023;
    int g0  = b * 1024 + sub * 128;
    const float* p = g_Apart + (size_t)g0 * D_ + d;
    float s = 0.f;
    #pragma unroll 8
    for (int g = 0; g < 128; g++) s += p[(size_t)g * D_];
    g_A8[sub * 4096 + rem] = s;
}

// ---------------- W'_b = A_b (*) W_out  -> bf16, 4 copies (folds stage-2 reduce) ------------
__global__ void __launch_bounds__(256) k_scaleW(const float* __restrict__ Wout)
{
    int i4 = (blockIdx.x * blockDim.x + threadIdx.x) * 4;   // over D_*D_
    if (i4 >= D_ * D_) return;
    int d = i4 & 1023;
    float4 w = *(const float4*)(Wout + i4);
    #pragma unroll
    for (int b = 0; b < B_; b++) {
        float4 a = make_float4(0.f, 0.f, 0.f, 0.f);
        #pragma unroll
        for (int sub = 0; sub < 8; sub++) {
            float4 t = *(const float4*)(g_A8 + sub * 4096 + b * 1024 + d);
            a.x += t.x; a.y += t.y; a.z += t.z; a.w += t.w;
        }
        __nv_bfloat16* dst = g_Wpr + (size_t)b * D_ * D_ + i4;
        *(__nv_bfloat162*)(dst)     = __floats2bfloat162_rn(w.x * a.x, w.y * a.y);
        *(__nv_bfloat162*)(dst + 2) = __floats2bfloat162_rn(w.z * a.z, w.w * a.w);
    }
}

// ---------------- LayerNorm: warp-per-row, no barriers ----------------
__global__ void __launch_bounds__(256) k_layernorm(
    const float* __restrict__ X, const float* __restrict__ lg, const float* __restrict__ lb)
{
    const int w    = threadIdx.x >> 5;
    const int lane = threadIdx.x & 31;
    const int row  = blockIdx.x * 8 + w;
    const int c0   = 4 * lane;
    const float* xp = X + (size_t)row * D_ + c0;

    float x[8][4];
    float s = 0.f, sq = 0.f;
    #pragma unroll
    for (int k = 0; k < 8; k++) {
        float4 v = *(const float4*)(xp + 128 * k);
        x[k][0] = v.x; x[k][1] = v.y; x[k][2] = v.z; x[k][3] = v.w;
        s  += v.x + v.y + v.z + v.w;
        sq += v.x * v.x + v.y * v.y + v.z * v.z + v.w * v.w;
    }
    #pragma unroll
    for (int o = 16; o; o >>= 1) {
        s  += __shfl_xor_sync(0xffffffffu, s, o);
        sq += __shfl_xor_sync(0xffffffffu, sq, o);
    }
    const float mu  = s * (1.f / D_);
    const float var = sq * (1.f / D_) - mu * mu;
    const float rs  = rsqrtf(var + 1e-5f);

    __nv_bfloat16* op = g_Xn + (size_t)row * D_ + c0;
    #pragma unroll
    for (int k = 0; k < 8; k++) {
        float4 g4 = *(const float4*)(lg + c0 + 128 * k);
        float4 b4 = *(const float4*)(lb + c0 + 128 * k);
        float y0 = (x[k][0] - mu) * rs * g4.x + b4.x;
        float y1 = (x[k][1] - mu) * rs * g4.y + b4.y;
        float y2 = (x[k][2] - mu) * rs * g4.z + b4.z;
        float y3 = (x[k][3] - mu) * rs * g4.w + b4.w;
        *(__nv_bfloat162*)(op + 128 * k)     = __floats2bfloat162_rn(y0, y1);
        *(__nv_bfloat162*)(op + 128 * k + 2) = __floats2bfloat162_rn(y2, y3);
    }
}

// ---------------- launch ----------------
extern "C" void kernel_launch(void* const* d_in, const int* in_sizes, int n_in,
                              void* d_out, int out_size)
{
    const float* X    = (const float*)d_in[0];
    const float* Win  = (const float*)d_in[1];
    const float* Wout = (const float*)d_in[2];
    const float* lg   = (const float*)d_in[3];
    const float* lb   = (const float*)d_in[4];
    float* out = (float*)d_out;

    cudaFuncSetAttribute(k_gemm, cudaFuncAttributeMaxDynamicSharedMemorySize, GEMM_SMEM);

    k_convert<<<(E3 * D_) / 4 / 256, 256>>>(Win, E3 * D_);
    k_rotfill<<<128, 256>>>();
    k_layernorm<<<NROWS / 8, 256>>>(X, lg, lb);
    k_gemm<<<dim3(E3 / 256, NROWS / 128), 256, GEMM_SMEM>>>(nullptr, nullptr, 0);
    k_rownorm<<<NROWS / 256, 256>>>();
    k_rowproc<<<NROWS / 16, 256>>>();
    k_reduceA<<<128, 256>>>();
    k_scaleW<<<D_ * D_ / 4 / 256, 256>>>(Wout);
    k_gemm<<<dim3(D_ / 256, NROWS / 128), 256, GEMM_SMEM>>>(X, out, 1);
}

// round 12
// speedup vs baseline: 1.1137x; 1.0165x over previous
#include <cuda_runtime.h>
#include <cuda_bf16.h>
#include <math.h>
#include <stdint.h>

#define D_      1024
#define S_      8192
#define B_      4
#define NROWS   (B_ * S_)      // 32768
#define E3      (3 * D_)       // 3072

// ---------------- scratch (static __device__: allocation-free) ----------------
__device__ __nv_bfloat16 g_Xn  [(size_t)NROWS * D_];   // 64 MiB
__device__ __nv_bfloat16 g_Win [(size_t)E3 * D_];      // 6 MiB
__device__ __nv_bfloat16 g_Wpr [(size_t)B_ * D_ * D_]; // 8 MiB  (A-scaled W_out, per batch)
__device__ __nv_bfloat16 g_Qb  [(size_t)NROWS * D_];   // 64 MiB
__device__ __nv_bfloat16 g_Kb  [(size_t)NROWS * D_];   // 64 MiB
__device__ __nv_bfloat16 g_Vb  [(size_t)NROWS * D_];   // 64 MiB
__device__ float         g_npQ [(size_t)NROWS * 32];   // 4 MiB  (per-row sq-norm partials)
__device__ float         g_npK [(size_t)NROWS * 32];   // 4 MiB
__device__ float2        g_rn  [(size_t)NROWS];        // 256 KiB (qi, ki per row)
__device__ float2        g_rot [(size_t)S_ * 256];     // 16 MiB  (cos,sin per (s, pair))
__device__ float         g_Apart[(size_t)4096 * D_];   // 16 MiB
__device__ float         g_A8  [8 * B_ * D_];
__device__ __nv_bfloat16 g_Y   [(size_t)NROWS * D_];   // 64 MiB (Qhat, bf16)

__device__ __forceinline__ uint32_t smem_u32(const void* p) {
    uint32_t a;
    asm("{ .reg .u64 t; cvta.to.shared.u64 t, %1; cvt.u32.u64 %0, t; }" : "=r"(a) : "l"(p));
    return a;
}

// ---------------- fp32 -> bf16 weight conversion (W_in) ----------------
__global__ void k_convert(const float* __restrict__ src, int n)
{
    int i = (blockIdx.x * blockDim.x + threadIdx.x) * 4;
    if (i >= n) return;
    float4 v = *(const float4*)(src + i);
    *(__nv_bfloat162*)(g_Win + i)     = __floats2bfloat162_rn(v.x, v.y);
    *(__nv_bfloat162*)(g_Win + i + 2) = __floats2bfloat162_rn(v.z, v.w);
}

// ---------------- rotary cos/sin table: anchor + 64-step recurrence ----------------
__global__ void k_rotfill()
{
    int id = blockIdx.x * blockDim.x + threadIdx.x;   // 0..32767
    int p  = id & 255;
    int sg = id >> 8;          // 0..127
    int s0 = sg * 64;
    double invf = pow(10000.0, -(double)p * (1.0 / 256.0));
    double th0  = fmod((double)s0 * invf, 6.283185307179586476925286766559);
    float c, s, cf, sf;
    sincosf((float)th0, &s, &c);
    sincosf((float)invf, &sf, &cf);
    float2* dst = g_rot + (size_t)s0 * 256 + p;
    #pragma unroll 8
    for (int j = 0; j < 64; j++) {
        *dst = make_float2(c, s);
        dst += 256;
        float nc = c * cf - s * sf;
        float ns = s * cf + c * sf;
        c = nc; s = ns;
    }
}

// ---------------- per-row inverse norms from GEMM1 partials ----------------
__global__ void k_rownorm()
{
    int row = blockIdx.x * blockDim.x + threadIdx.x;   // 0..NROWS-1
    const float4* npq = (const float4*)(g_npQ + (size_t)row * 32);
    const float4* npk = (const float4*)(g_npK + (size_t)row * 32);
    float qs = 0.f, ks = 0.f;
    #pragma unroll
    for (int i = 0; i < 8; i++) {
        float4 tq = npq[i];
        float4 tk = npk[i];
        qs += tq.x + tq.y + tq.z + tq.w;
        ks += tk.x + tk.y + tk.z + tk.w;
    }
    g_rn[row] = make_float2(rsqrtf(qs + 1e-6f), rsqrtf(ks + 1e-6f));
}

// ---------------- mma.sync bf16 GEMM ----------------
// 128x128 block tile, 8 warps (2m x 4n), warp tile 64x32, KC=64, 3-stage cp.async,
// 2 CTAs/SM (cross-CTA overlap hides barrier/wait skew).
#define KC 64
#define NCHUNK 16
#define ASTAGE 16384
#define BSTAGE 16384
#define STAGE_BYTES (ASTAGE + BSTAGE)     // 32 KB
#define GEMM_SMEM (3 * STAGE_BYTES)       // 96 KB

__global__ void __launch_bounds__(256, 2) k_gemm(
    const float* __restrict__ addX, float* __restrict__ Cout, int mode)
{
    extern __shared__ char smem[];
    const int K = 1024;
    const int tid  = threadIdx.x;
    const int w    = tid >> 5;
    const int lane = tid & 31;
    const int wm   = w & 1;          // 0..1 -> 64-row slice
    const int wn   = w >> 1;         // 0..3 -> 32-col slice
    const int m0 = blockIdx.y * 128;
    const int n0 = blockIdx.x * 128;

    const __nv_bfloat16* Ag = mode ? g_Y : g_Xn;
    const __nv_bfloat16* Bg = mode ? (g_Wpr + (size_t)(m0 >> 13) * D_ * D_) : g_Win;

    const uint32_t sbase = smem_u32(smem);

    // chunk copy = 2048 vectors (A 1024 + B 1024); thread does 8, 2 per piece
    auto issue_piece = [&](int kt, int p) {
        const uint32_t st = sbase + (kt % 3) * STAGE_BYTES;
        #pragma unroll
        for (int i = 2 * p; i < 2 * p + 2; i++) {
            int vec = i * 256 + tid;
            int isB = vec >= 1024;
            int vv  = vec & 1023;
            int row = vv >> 3;
            int c   = vv & 7;
            const __nv_bfloat16* src =
                (isB ? Bg + (size_t)(n0 + row) * K : Ag + (size_t)(m0 + row) * K)
                + kt * KC + c * 8;
            uint32_t dst = st + (isB ? ASTAGE : 0) + row * 128 + (((c ^ (row & 7)) << 4));
            asm volatile("cp.async.cg.shared.global [%0], [%1], 16;" :: "r"(dst), "l"(src));
        }
    };
    auto issue_all = [&](int kt) {
        #pragma unroll
        for (int p = 0; p < 4; p++) issue_piece(kt, p);
        asm volatile("cp.async.commit_group;" ::: "memory");
    };

    float acc[4][4][4];
    #pragma unroll
    for (int mi = 0; mi < 4; mi++)
        #pragma unroll
        for (int ni = 0; ni < 4; ni++)
            #pragma unroll
            for (int e = 0; e < 4; e++) acc[mi][ni][e] = 0.f;

    issue_all(0); issue_all(1);

    const int lr = lane & 15;
    const int lc = lane >> 4;

    for (int kt = 0; kt < NCHUNK; kt++) {
        asm volatile("cp.async.wait_group 1;" ::: "memory");
        __syncthreads();

        const uint32_t sA = sbase + (kt % 3) * STAGE_BYTES;
        const uint32_t sB = sA + ASTAGE;
        const bool doIssue = (kt + 2 < NCHUNK);

        #pragma unroll
        for (int ks = 0; ks < 4; ks++) {
            uint32_t a[4][4], b[4][2];
            const int c = ks * 2 + lc;
            #pragma unroll
            for (int mi = 0; mi < 4; mi++) {
                int r = wm * 64 + mi * 16 + lr;
                uint32_t addr = sA + r * 128 + ((c ^ (r & 7)) << 4);
                asm volatile("ldmatrix.sync.aligned.m8n8.x4.shared.b16 {%0,%1,%2,%3}, [%4];"
                    : "=r"(a[mi][0]), "=r"(a[mi][1]), "=r"(a[mi][2]), "=r"(a[mi][3])
                    : "r"(addr));
            }
            #pragma unroll
            for (int nb = 0; nb < 2; nb++) {
                int r = wn * 32 + nb * 16 + lr;
                uint32_t addr = sB + r * 128 + ((c ^ (r & 7)) << 4);
                uint32_t t0, t1, t2, t3;
                asm volatile("ldmatrix.sync.aligned.m8n8.x4.shared.b16 {%0,%1,%2,%3}, [%4];"
                    : "=r"(t0), "=r"(t1), "=r"(t2), "=r"(t3) : "r"(addr));
                b[nb * 2][0] = t0; b[nb * 2][1] = t2;
                b[nb * 2 + 1][0] = t1; b[nb * 2 + 1][1] = t3;
            }

            if (doIssue) issue_piece(kt + 2, ks);

            #pragma unroll
            for (int mi = 0; mi < 4; mi++)
                #pragma unroll
                for (int ni = 0; ni < 4; ni++) {
                    asm volatile(
                        "mma.sync.aligned.m16n8k16.row.col.f32.bf16.bf16.f32 "
                        "{%0,%1,%2,%3}, {%4,%5,%6,%7}, {%8,%9}, {%0,%1,%2,%3};"
                        : "+f"(acc[mi][ni][0]), "+f"(acc[mi][ni][1]),
                          "+f"(acc[mi][ni][2]), "+f"(acc[mi][ni][3])
                        : "r"(a[mi][0]), "r"(a[mi][1]), "r"(a[mi][2]), "r"(a[mi][3]),
                          "r"(b[ni][0]), "r"(b[ni][1]));
                }
        }
        asm volatile("cp.async.commit_group;" ::: "memory");
    }

    const int rbase = m0 + wm * 64 + (lane >> 2);
    if (mode) {
        const int cbase = n0 + wn * 32 + (lane & 3) * 2;
        #pragma unroll
        for (int mi = 0; mi < 4; mi++)
            #pragma unroll
            for (int ni = 0; ni < 4; ni++) {
                int rr = rbase + mi * 16;
                int cc = cbase + ni * 8;
                size_t i0 = (size_t)rr * D_ + cc;
                size_t i1 = (size_t)(rr + 8) * D_ + cc;
                float2 x0 = *(const float2*)(addX + i0);
                float2 x1 = *(const float2*)(addX + i1);
                *(float2*)(Cout + i0) = make_float2(acc[mi][ni][0] + x0.x, acc[mi][ni][1] + x0.y);
                *(float2*)(Cout + i1) = make_float2(acc[mi][ni][2] + x1.x, acc[mi][ni][3] + x1.y);
            }
    } else {
        const int region = n0 >> 10;           // 0=Q, 1=K, 2=V
        const int cbase  = (n0 & 1023) + wn * 32 + (lane & 3) * 2;
        __nv_bfloat16* Cb = (region == 0) ? g_Qb : (region == 1) ? g_Kb : g_Vb;
        if (region < 2) {
            float* np = region ? g_npK : g_npQ;
            const int widx = ((n0 & 1023) >> 5) + wn;     // 0..31 stripe index
            #pragma unroll
            for (int mi = 0; mi < 4; mi++) {
                float s0 = 0.f, s1 = 0.f;
                #pragma unroll
                for (int ni = 0; ni < 4; ni++) {
                    int rr = rbase + mi * 16;
                    int cc = cbase + ni * 8;
                    *(__nv_bfloat162*)(Cb + (size_t)rr * D_ + cc) =
                        __floats2bfloat162_rn(acc[mi][ni][0], acc[mi][ni][1]);
                    *(__nv_bfloat162*)(Cb + (size_t)(rr + 8) * D_ + cc) =
                        __floats2bfloat162_rn(acc[mi][ni][2], acc[mi][ni][3]);
                    s0 += acc[mi][ni][0] * acc[mi][ni][0] + acc[mi][ni][1] * acc[mi][ni][1];
                    s1 += acc[mi][ni][2] * acc[mi][ni][2] + acc[mi][ni][3] * acc[mi][ni][3];
                }
                s0 += __shfl_xor_sync(0xffffffffu, s0, 1);
                s0 += __shfl_xor_sync(0xffffffffu, s0, 2);
                s1 += __shfl_xor_sync(0xffffffffu, s1, 1);
                s1 += __shfl_xor_sync(0xffffffffu, s1, 2);
                if ((lane & 3) == 0) {
                    int rr = rbase + mi * 16;
                    np[(size_t)rr * 32 + widx]       = s0;
                    np[(size_t)(rr + 8) * 32 + widx] = s1;
                }
            }
        } else {
            #pragma unroll
            for (int mi = 0; mi < 4; mi++)
                #pragma unroll
                for (int ni = 0; ni < 4; ni++) {
                    int rr = rbase + mi * 16;
                    int cc = cbase + ni * 8;
                    *(__nv_bfloat162*)(Cb + (size_t)rr * D_ + cc) =
                        __floats2bfloat162_rn(acc[mi][ni][0], acc[mi][ni][1]);
                    *(__nv_bfloat162*)(Cb + (size_t)(rr + 8) * D_ + cc) =
                        __floats2bfloat162_rn(acc[mi][ni][2], acc[mi][ni][3]);
                }
        }
    }
}

// ---------------- rotary + scale + A partials : fully parallel streaming ----------------
__global__ void __launch_bounds__(256) k_rowproc()
{
    const int tid = threadIdx.x;
    const int r2  = tid >> 7;            // 0..1
    const int c   = tid & 127;           // col block
    const int col = c * 8;
    const bool rot = (col < 512);
    const int rowbase = blockIdx.x * 16 + r2 * 8;

    float accA[8];
    #pragma unroll
    for (int j = 0; j < 8; j++) accA[j] = 0.f;

    #pragma unroll 2
    for (int it = 0; it < 8; it++) {
        const int row = rowbase + it;
        const size_t base = (size_t)row * D_ + col;
        const float2 rn = g_rn[row];                  // (qi, ki) broadcast

        uint4 qu = *(const uint4*)(g_Qb + base);
        uint4 ku = *(const uint4*)(g_Kb + base);
        uint4 vu = *(const uint4*)(g_Vb + base);

        float2 q[4], k[4], v[4];
        #pragma unroll
        for (int j = 0; j < 4; j++) {
            q[j] = __bfloat1622float2(((const __nv_bfloat162*)&qu)[j]);
            k[j] = __bfloat1622float2(((const __nv_bfloat162*)&ku)[j]);
            v[j] = __bfloat1622float2(((const __nv_bfloat162*)&vu)[j]);
        }

        if (rot) {
            const float4* rp = (const float4*)(g_rot + (size_t)(row & 8191) * 256 + (col >> 1));
            float4 r01 = rp[0];
            float4 r23 = rp[1];
            float cs[4] = { r01.x, r01.z, r23.x, r23.z };
            float sn[4] = { r01.y, r01.w, r23.y, r23.w };
            #pragma unroll
            for (int j = 0; j < 4; j++) {
                float a, bb;
                a = q[j].x * cs[j] - q[j].y * sn[j];
                bb = q[j].y * cs[j] + q[j].x * sn[j];
                q[j].x = a; q[j].y = bb;
                a = k[j].x * cs[j] - k[j].y * sn[j];
                bb = k[j].y * cs[j] + k[j].x * sn[j];
                k[j].x = a; k[j].y = bb;
            }
        }

        uint4 yo;
        #pragma unroll
        for (int j = 0; j < 4; j++) {
            accA[2 * j]     += k[j].x * rn.y * v[j].x;
            accA[2 * j + 1] += k[j].y * rn.y * v[j].y;
            ((__nv_bfloat162*)&yo)[j] = __floats2bfloat162_rn(q[j].x * rn.x, q[j].y * rn.x);
        }
        *(uint4*)(g_Y + base) = yo;
    }

    float* ap = g_Apart + (size_t)(blockIdx.x * 2 + r2) * D_ + col;
    *(float4*)(ap)     = make_float4(accA[0], accA[1], accA[2], accA[3]);
    *(float4*)(ap + 4) = make_float4(accA[4], accA[5], accA[6], accA[7]);
}

// ---------------- reduce A partials (stage 1: 4096 groups -> 8x per (b,d)) ----------------
__global__ void k_reduceA()
{
    int idx = blockIdx.x * blockDim.x + threadIdx.x;   // 0..32767
    int sub = idx >> 12;       // 0..7
    int rem = idx & 4095;      // b*1024 + d
    int b   = rem >> 10;
    int d   = rem & 1023;
    int g0  = b * 1024 + sub * 128;
    const float* p = g_Apart + (size_t)g0 * D_ + d;
    float s = 0.f;
    #pragma unroll 8
    for (int g = 0; g < 128; g++) s += p[(size_t)g * D_];
    g_A8[sub * 4096 + rem] = s;
}

// ---------------- W'_b = A_b (*) W_out  -> bf16, 4 copies (folds stage-2 reduce) ------------
__global__ void __launch_bounds__(256) k_scaleW(const float* __restrict__ Wout)
{
    int i4 = (blockIdx.x * blockDim.x + threadIdx.x) * 4;   // over D_*D_
    if (i4 >= D_ * D_) return;
    int d = i4 & 1023;
    float4 w = *(const float4*)(Wout + i4);
    #pragma unroll
    for (int b = 0; b < B_; b++) {
        float4 a = make_float4(0.f, 0.f, 0.f, 0.f);
        #pragma unroll
        for (int sub = 0; sub < 8; sub++) {
            float4 t = *(const float4*)(g_A8 + sub * 4096 + b * 1024 + d);
            a.x += t.x; a.y += t.y; a.z += t.z; a.w += t.w;
        }
        __nv_bfloat16* dst = g_Wpr + (size_t)b * D_ * D_ + i4;
        *(__nv_bfloat162*)(dst)     = __floats2bfloat162_rn(w.x * a.x, w.y * a.y);
        *(__nv_bfloat162*)(dst + 2) = __floats2bfloat162_rn(w.z * a.z, w.w * a.w);
    }
}

// ---------------- LayerNorm: warp-per-row, no barriers ----------------
__global__ void __launch_bounds__(256) k_layernorm(
    const float* __restrict__ X, const float* __restrict__ lg, const float* __restrict__ lb)
{
    const int w    = threadIdx.x >> 5;
    const int lane = threadIdx.x & 31;
    const int row  = blockIdx.x * 8 + w;
    const int c0   = 4 * lane;
    const float* xp = X + (size_t)row * D_ + c0;

    float x[8][4];
    float s = 0.f, sq = 0.f;
    #pragma unroll
    for (int k = 0; k < 8; k++) {
        float4 v = *(const float4*)(xp + 128 * k);
        x[k][0] = v.x; x[k][1] = v.y; x[k][2] = v.z; x[k][3] = v.w;
        s  += v.x + v.y + v.z + v.w;
        sq += v.x * v.x + v.y * v.y + v.z * v.z + v.w * v.w;
    }
    #pragma unroll
    for (int o = 16; o; o >>= 1) {
        s  += __shfl_xor_sync(0xffffffffu, s, o);
        sq += __shfl_xor_sync(0xffffffffu, sq, o);
    }
    const float mu  = s * (1.f / D_);
    const float var = sq * (1.f / D_) - mu * mu;
    const float rs  = rsqrtf(var + 1e-5f);

    __nv_bfloat16* op = g_Xn + (size_t)row * D_ + c0;
    #pragma unroll
    for (int k = 0; k < 8; k++) {
        float4 g4 = *(const float4*)(lg + c0 + 128 * k);
        float4 b4 = *(const float4*)(lb + c0 + 128 * k);
        float y0 = (x[k][0] - mu) * rs * g4.x + b4.x;
        float y1 = (x[k][1] - mu) * rs * g4.y + b4.y;
        float y2 = (x[k][2] - mu) * rs * g4.z + b4.z;
        float y3 = (x[k][3] - mu) * rs * g4.w + b4.w;
        *(__nv_bfloat162*)(op + 128 * k)     = __floats2bfloat162_rn(y0, y1);
        *(__nv_bfloat162*)(op + 128 * k + 2) = __floats2bfloat162_rn(y2, y3);
    }
}

// ---------------- launch ----------------
extern "C" void kernel_launch(void* const* d_in, const int* in_sizes, int n_in,
                              void* d_out, int out_size)
{
    const float* X    = (const float*)d_in[0];
    const float* Win  = (const float*)d_in[1];
    const float* Wout = (const float*)d_in[2];
    const float* lg   = (const float*)d_in[3];
    const float* lb   = (const float*)d_in[4];
    float* out = (float*)d_out;

    cudaFuncSetAttribute(k_gemm, cudaFuncAttributeMaxDynamicSharedMemorySize, GEMM_SMEM);

    k_convert<<<(E3 * D_) / 4 / 256, 256>>>(Win, E3 * D_);
    k_rotfill<<<128, 256>>>();
    k_layernorm<<<NROWS / 8, 256>>>(X, lg, lb);
    k_gemm<<<dim3(E3 / 128, NROWS / 128), 256, GEMM_SMEM>>>(nullptr, nullptr, 0);
    k_rownorm<<<NROWS / 256, 256>>>();
    k_rowproc<<<NROWS / 16, 256>>>();
    k_reduceA<<<128, 256>>>();
    k_scaleW<<<D_ * D_ / 4 / 256, 256>>>(Wout);
    k_gemm<<<dim3(D_ / 128, NROWS / 128), 256, GEMM_SMEM>>>(X, out, 1);
}

// round 13
// speedup vs baseline: 1.1291x; 1.0139x over previous
#include <cuda_runtime.h>
#include <cuda_bf16.h>
#include <math.h>
#include <stdint.h>

#define D_      1024
#define S_      8192
#define B_      4
#define NROWS   (B_ * S_)      // 32768
#define E3      (3 * D_)       // 3072

// ---------------- scratch (static __device__: allocation-free) ----------------
__device__ __nv_bfloat16 g_Xn  [(size_t)NROWS * D_];   // 64 MiB
__device__ __nv_bfloat16 g_Win [(size_t)E3 * D_];      // 6 MiB
__device__ __nv_bfloat16 g_Wpr [(size_t)B_ * D_ * D_]; // 8 MiB  (A-scaled W_out, per batch)
__device__ __nv_bfloat16 g_Qb  [(size_t)NROWS * D_];   // 64 MiB
__device__ __nv_bfloat16 g_Kb  [(size_t)NROWS * D_];   // 64 MiB
__device__ __nv_bfloat16 g_Vb  [(size_t)NROWS * D_];   // 64 MiB
__device__ float         g_npQ [(size_t)NROWS * 16];   // 2 MiB  (per-row sq-norm partials)
__device__ float         g_npK [(size_t)NROWS * 16];   // 2 MiB
__device__ float2        g_rn  [(size_t)NROWS];        // 256 KiB (qi, ki per row)
__device__ float2        g_rot [(size_t)S_ * 256];     // 16 MiB  (cos,sin per (s, pair))
__device__ float         g_Apart[(size_t)4096 * D_];   // 16 MiB
__device__ float         g_A8  [8 * B_ * D_];
__device__ __nv_bfloat16 g_Y   [(size_t)NROWS * D_];   // 64 MiB (Qhat, bf16)

__device__ __forceinline__ uint32_t smem_u32(const void* p) {
    uint32_t a;
    asm("{ .reg .u64 t; cvta.to.shared.u64 t, %1; cvt.u32.u64 %0, t; }" : "=r"(a) : "l"(p));
    return a;
}

// ---------------- fp32 -> bf16 weight conversion (W_in) ----------------
__global__ void k_convert(const float* __restrict__ src, int n)
{
    int i = (blockIdx.x * blockDim.x + threadIdx.x) * 4;
    if (i >= n) return;
    float4 v = *(const float4*)(src + i);
    *(__nv_bfloat162*)(g_Win + i)     = __floats2bfloat162_rn(v.x, v.y);
    *(__nv_bfloat162*)(g_Win + i + 2) = __floats2bfloat162_rn(v.z, v.w);
}

// ---------------- rotary cos/sin table: anchor + 64-step recurrence ----------------
__global__ void k_rotfill()
{
    int id = blockIdx.x * blockDim.x + threadIdx.x;   // 0..32767
    int p  = id & 255;
    int sg = id >> 8;          // 0..127
    int s0 = sg * 64;
    double invf = pow(10000.0, -(double)p * (1.0 / 256.0));
    double th0  = fmod((double)s0 * invf, 6.283185307179586476925286766559);
    float c, s, cf, sf;
    sincosf((float)th0, &s, &c);
    sincosf((float)invf, &sf, &cf);
    float2* dst = g_rot + (size_t)s0 * 256 + p;
    #pragma unroll 8
    for (int j = 0; j < 64; j++) {
        *dst = make_float2(c, s);
        dst += 256;
        float nc = c * cf - s * sf;
        float ns = s * cf + c * sf;
        c = nc; s = ns;
    }
}

// ---------------- per-row inverse norms from GEMM1 partials ----------------
__global__ void k_rownorm()
{
    int row = blockIdx.x * blockDim.x + threadIdx.x;   // 0..NROWS-1
    const float4* npq = (const float4*)(g_npQ + (size_t)row * 16);
    const float4* npk = (const float4*)(g_npK + (size_t)row * 16);
    float qs = 0.f, ks = 0.f;
    #pragma unroll
    for (int i = 0; i < 4; i++) {
        float4 tq = npq[i];
        float4 tk = npk[i];
        qs += tq.x + tq.y + tq.z + tq.w;
        ks += tk.x + tk.y + tk.z + tk.w;
    }
    g_rn[row] = make_float2(rsqrtf(qs + 1e-6f), rsqrtf(ks + 1e-6f));
}

// ---------------- mma.sync bf16 GEMM ----------------
// 128x128 block tile, 4 warps (2m x 2n), warp tile 64x64, KC=64, 3-stage cp.async,
// 128 threads/CTA, 2 CTAs/SM: good LDSM:HMMA ratio AND cross-CTA overlap.
#define KC 64
#define NCHUNK 16
#define ASTAGE 16384
#define BSTAGE 16384
#define STAGE_BYTES (ASTAGE + BSTAGE)     // 32 KB
#define GEMM_SMEM (3 * STAGE_BYTES)       // 96 KB

__global__ void __launch_bounds__(128, 2) k_gemm(
    const float* __restrict__ addX, float* __restrict__ Cout, int mode)
{
    extern __shared__ char smem[];
    const int K = 1024;
    const int tid  = threadIdx.x;
    const int w    = tid >> 5;
    const int lane = tid & 31;
    const int wm   = w & 1;          // 0..1 -> 64-row slice
    const int wn   = w >> 1;         // 0..1 -> 64-col slice
    const int m0 = blockIdx.y * 128;
    const int n0 = blockIdx.x * 128;

    const __nv_bfloat16* Ag = mode ? g_Y : g_Xn;
    const __nv_bfloat16* Bg = mode ? (g_Wpr + (size_t)(m0 >> 13) * D_ * D_) : g_Win;

    const uint32_t sbase = smem_u32(smem);

    // chunk copy = 2048 vectors (A 1024 + B 1024); 128 threads -> 16/thread, 4 per piece
    auto issue_piece = [&](int kt, int p) {
        const uint32_t st = sbase + (kt % 3) * STAGE_BYTES;
        #pragma unroll
        for (int i = 4 * p; i < 4 * p + 4; i++) {
            int vec = i * 128 + tid;
            int isB = vec >= 1024;
            int vv  = vec & 1023;
            int row = vv >> 3;
            int c   = vv & 7;
            const __nv_bfloat16* src =
                (isB ? Bg + (size_t)(n0 + row) * K : Ag + (size_t)(m0 + row) * K)
                + kt * KC + c * 8;
            uint32_t dst = st + (isB ? ASTAGE : 0) + row * 128 + (((c ^ (row & 7)) << 4));
            asm volatile("cp.async.cg.shared.global [%0], [%1], 16;" :: "r"(dst), "l"(src));
        }
    };
    auto issue_all = [&](int kt) {
        #pragma unroll
        for (int p = 0; p < 4; p++) issue_piece(kt, p);
        asm volatile("cp.async.commit_group;" ::: "memory");
    };

    float acc[4][8][4];
    #pragma unroll
    for (int mi = 0; mi < 4; mi++)
        #pragma unroll
        for (int ni = 0; ni < 8; ni++)
            #pragma unroll
            for (int e = 0; e < 4; e++) acc[mi][ni][e] = 0.f;

    issue_all(0); issue_all(1);

    const int lr = lane & 15;
    const int lc = lane >> 4;

    for (int kt = 0; kt < NCHUNK; kt++) {
        asm volatile("cp.async.wait_group 1;" ::: "memory");
        __syncthreads();

        const uint32_t sA = sbase + (kt % 3) * STAGE_BYTES;
        const uint32_t sB = sA + ASTAGE;
        const bool doIssue = (kt + 2 < NCHUNK);

        #pragma unroll
        for (int ks = 0; ks < 4; ks++) {
            uint32_t a[4][4], b[8][2];
            const int c = ks * 2 + lc;
            #pragma unroll
            for (int mi = 0; mi < 4; mi++) {
                int r = wm * 64 + mi * 16 + lr;
                uint32_t addr = sA + r * 128 + ((c ^ (r & 7)) << 4);
                asm volatile("ldmatrix.sync.aligned.m8n8.x4.shared.b16 {%0,%1,%2,%3}, [%4];"
                    : "=r"(a[mi][0]), "=r"(a[mi][1]), "=r"(a[mi][2]), "=r"(a[mi][3])
                    : "r"(addr));
            }
            #pragma unroll
            for (int nb = 0; nb < 4; nb++) {
                int r = wn * 64 + nb * 16 + lr;
                uint32_t addr = sB + r * 128 + ((c ^ (r & 7)) << 4);
                uint32_t t0, t1, t2, t3;
                asm volatile("ldmatrix.sync.aligned.m8n8.x4.shared.b16 {%0,%1,%2,%3}, [%4];"
                    : "=r"(t0), "=r"(t1), "=r"(t2), "=r"(t3) : "r"(addr));
                b[nb * 2][0] = t0; b[nb * 2][1] = t2;
                b[nb * 2 + 1][0] = t1; b[nb * 2 + 1][1] = t3;
            }

            if (doIssue) issue_piece(kt + 2, ks);

            #pragma unroll
            for (int mi = 0; mi < 4; mi++)
                #pragma unroll
                for (int ni = 0; ni < 8; ni++) {
                    asm volatile(
                        "mma.sync.aligned.m16n8k16.row.col.f32.bf16.bf16.f32 "
                        "{%0,%1,%2,%3}, {%4,%5,%6,%7}, {%8,%9}, {%0,%1,%2,%3};"
                        : "+f"(acc[mi][ni][0]), "+f"(acc[mi][ni][1]),
                          "+f"(acc[mi][ni][2]), "+f"(acc[mi][ni][3])
                        : "r"(a[mi][0]), "r"(a[mi][1]), "r"(a[mi][2]), "r"(a[mi][3]),
                          "r"(b[ni][0]), "r"(b[ni][1]));
                }
        }
        asm volatile("cp.async.commit_group;" ::: "memory");
    }

    const int rbase = m0 + wm * 64 + (lane >> 2);
    if (mode) {
        const int cbase = n0 + wn * 64 + (lane & 3) * 2;
        #pragma unroll
        for (int mi = 0; mi < 4; mi++)
            #pragma unroll
            for (int ni = 0; ni < 8; ni++) {
                int rr = rbase + mi * 16;
                int cc = cbase + ni * 8;
                size_t i0 = (size_t)rr * D_ + cc;
                size_t i1 = (size_t)(rr + 8) * D_ + cc;
                float2 x0 = *(const float2*)(addX + i0);
                float2 x1 = *(const float2*)(addX + i1);
                *(float2*)(Cout + i0) = make_float2(acc[mi][ni][0] + x0.x, acc[mi][ni][1] + x0.y);
                *(float2*)(Cout + i1) = make_float2(acc[mi][ni][2] + x1.x, acc[mi][ni][3] + x1.y);
            }
    } else {
        const int region = n0 >> 10;           // 0=Q, 1=K, 2=V
        const int cbase  = (n0 & 1023) + wn * 64 + (lane & 3) * 2;
        __nv_bfloat16* Cb = (region == 0) ? g_Qb : (region == 1) ? g_Kb : g_Vb;
        if (region < 2) {
            float* np = region ? g_npK : g_npQ;
            const int widx = ((n0 & 1023) >> 6) + wn;     // 0..15 stripe (64 cols each)
            #pragma unroll
            for (int mi = 0; mi < 4; mi++) {
                float s0 = 0.f, s1 = 0.f;
                #pragma unroll
                for (int ni = 0; ni < 8; ni++) {
                    int rr = rbase + mi * 16;
                    int cc = cbase + ni * 8;
                    *(__nv_bfloat162*)(Cb + (size_t)rr * D_ + cc) =
                        __floats2bfloat162_rn(acc[mi][ni][0], acc[mi][ni][1]);
                    *(__nv_bfloat162*)(Cb + (size_t)(rr + 8) * D_ + cc) =
                        __floats2bfloat162_rn(acc[mi][ni][2], acc[mi][ni][3]);
                    s0 += acc[mi][ni][0] * acc[mi][ni][0] + acc[mi][ni][1] * acc[mi][ni][1];
                    s1 += acc[mi][ni][2] * acc[mi][ni][2] + acc[mi][ni][3] * acc[mi][ni][3];
                }
                s0 += __shfl_xor_sync(0xffffffffu, s0, 1);
                s0 += __shfl_xor_sync(0xffffffffu, s0, 2);
                s1 += __shfl_xor_sync(0xffffffffu, s1, 1);
                s1 += __shfl_xor_sync(0xffffffffu, s1, 2);
                if ((lane & 3) == 0) {
                    int rr = rbase + mi * 16;
                    np[(size_t)rr * 16 + widx]       = s0;
                    np[(size_t)(rr + 8) * 16 + widx] = s1;
                }
            }
        } else {
            #pragma unroll
            for (int mi = 0; mi < 4; mi++)
                #pragma unroll
                for (int ni = 0; ni < 8; ni++) {
                    int rr = rbase + mi * 16;
                    int cc = cbase + ni * 8;
                    *(__nv_bfloat162*)(Cb + (size_t)rr * D_ + cc) =
                        __floats2bfloat162_rn(acc[mi][ni][0], acc[mi][ni][1]);
                    *(__nv_bfloat162*)(Cb + (size_t)(rr + 8) * D_ + cc) =
                        __floats2bfloat162_rn(acc[mi][ni][2], acc[mi][ni][3]);
                }
        }
    }
}

// ---------------- rotary + scale + A partials : fully parallel streaming ----------------
__global__ void __launch_bounds__(256) k_rowproc()
{
    const int tid = threadIdx.x;
    const int r2  = tid >> 7;            // 0..1
    const int c   = tid & 127;           // col block
    const int col = c * 8;
    const bool rot = (col < 512);
    const int rowbase = blockIdx.x * 16 + r2 * 8;

    float accA[8];
    #pragma unroll
    for (int j = 0; j < 8; j++) accA[j] = 0.f;

    #pragma unroll 2
    for (int it = 0; it < 8; it++) {
        const int row = rowbase + it;
        const size_t base = (size_t)row * D_ + col;
        const float2 rn = g_rn[row];                  // (qi, ki) broadcast

        uint4 qu = *(const uint4*)(g_Qb + base);
        uint4 ku = *(const uint4*)(g_Kb + base);
        uint4 vu = *(const uint4*)(g_Vb + base);

        float2 q[4], k[4], v[4];
        #pragma unroll
        for (int j = 0; j < 4; j++) {
            q[j] = __bfloat1622float2(((const __nv_bfloat162*)&qu)[j]);
            k[j] = __bfloat1622float2(((const __nv_bfloat162*)&ku)[j]);
            v[j] = __bfloat1622float2(((const __nv_bfloat162*)&vu)[j]);
        }

        if (rot) {
            const float4* rp = (const float4*)(g_rot + (size_t)(row & 8191) * 256 + (col >> 1));
            float4 r01 = rp[0];
            float4 r23 = rp[1];
            float cs[4] = { r01.x, r01.z, r23.x, r23.z };
            float sn[4] = { r01.y, r01.w, r23.y, r23.w };
            #pragma unroll
            for (int j = 0; j < 4; j++) {
                float a, bb;
                a = q[j].x * cs[j] - q[j].y * sn[j];
                bb = q[j].y * cs[j] + q[j].x * sn[j];
                q[j].x = a; q[j].y = bb;
                a = k[j].x * cs[j] - k[j].y * sn[j];
                bb = k[j].y * cs[j] + k[j].x * sn[j];
                k[j].x = a; k[j].y = bb;
            }
        }

        uint4 yo;
        #pragma unroll
        for (int j = 0; j < 4; j++) {
            accA[2 * j]     += k[j].x * rn.y * v[j].x;
            accA[2 * j + 1] += k[j].y * rn.y * v[j].y;
            ((__nv_bfloat162*)&yo)[j] = __floats2bfloat162_rn(q[j].x * rn.x, q[j].y * rn.x);
        }
        *(uint4*)(g_Y + base) = yo;
    }

    float* ap = g_Apart + (size_t)(blockIdx.x * 2 + r2) * D_ + col;
    *(float4*)(ap)     = make_float4(accA[0], accA[1], accA[2], accA[3]);
    *(float4*)(ap + 4) = make_float4(accA[4], accA[5], accA[6], accA[7]);
}

// ---------------- reduce A partials (stage 1: 4096 groups -> 8x per (b,d)) ----------------
__global__ void k_reduceA()
{
    int idx = blockIdx.x * blockDim.x + threadIdx.x;   // 0..32767
    int sub = idx >> 12;       // 0..7
    int rem = idx & 4095;      // b*1024 + d
    int b   = rem >> 10;
    int d   = rem & 1023;
    int g0  = b * 1024 + sub * 128;
    const float* p = g_Apart + (size_t)g0 * D_ + d;
    float s = 0.f;
    #pragma unroll 8
    for (int g = 0; g < 128; g++) s += p[(size_t)g * D_];
    g_A8[sub * 4096 + rem] = s;
}

// ---------------- W'_b = A_b (*) W_out  -> bf16, 4 copies (folds stage-2 reduce) ------------
__global__ void __launch_bounds__(256) k_scaleW(const float* __restrict__ Wout)
{
    int i4 = (blockIdx.x * blockDim.x + threadIdx.x) * 4;   // over D_*D_
    if (i4 >= D_ * D_) return;
    int d = i4 & 1023;
    float4 w = *(const float4*)(Wout + i4);
    #pragma unroll
    for (int b = 0; b < B_; b++) {
        float4 a = make_float4(0.f, 0.f, 0.f, 0.f);
        #pragma unroll
        for (int sub = 0; sub < 8; sub++) {
            float4 t = *(const float4*)(g_A8 + sub * 4096 + b * 1024 + d);
            a.x += t.x; a.y += t.y; a.z += t.z; a.w += t.w;
        }
        __nv_bfloat16* dst = g_Wpr + (size_t)b * D_ * D_ + i4;
        *(__nv_bfloat162*)(dst)     = __floats2bfloat162_rn(w.x * a.x, w.y * a.y);
        *(__nv_bfloat162*)(dst + 2) = __floats2bfloat162_rn(w.z * a.z, w.w * a.w);
    }
}

// ---------------- LayerNorm: warp-per-row, no barriers ----------------
__global__ void __launch_bounds__(256) k_layernorm(
    const float* __restrict__ X, const float* __restrict__ lg, const float* __restrict__ lb)
{
    const int w    = threadIdx.x >> 5;
    const int lane = threadIdx.x & 31;
    const int row  = blockIdx.x * 8 + w;
    const int c0   = 4 * lane;
    const float* xp = X + (size_t)row * D_ + c0;

    float x[8][4];
    float s = 0.f, sq = 0.f;
    #pragma unroll
    for (int k = 0; k < 8; k++) {
        float4 v = *(const float4*)(xp + 128 * k);
        x[k][0] = v.x; x[k][1] = v.y; x[k][2] = v.z; x[k][3] = v.w;
        s  += v.x + v.y + v.z + v.w;
        sq += v.x * v.x + v.y * v.y + v.z * v.z + v.w * v.w;
    }
    #pragma unroll
    for (int o = 16; o; o >>= 1) {
        s  += __shfl_xor_sync(0xffffffffu, s, o);
        sq += __shfl_xor_sync(0xffffffffu, sq, o);
    }
    const float mu  = s * (1.f / D_);
    const float var = sq * (1.f / D_) - mu * mu;
    const float rs  = rsqrtf(var + 1e-5f);

    __nv_bfloat16* op = g_Xn + (size_t)row * D_ + c0;
    #pragma unroll
    for (int k = 0; k < 8; k++) {
        float4 g4 = *(const float4*)(lg + c0 + 128 * k);
        float4 b4 = *(const float4*)(lb + c0 + 128 * k);
        float y0 = (x[k][0] - mu) * rs * g4.x + b4.x;
        float y1 = (x[k][1] - mu) * rs * g4.y + b4.y;
        float y2 = (x[k][2] - mu) * rs * g4.z + b4.z;
        float y3 = (x[k][3] - mu) * rs * g4.w + b4.w;
        *(__nv_bfloat162*)(op + 128 * k)     = __floats2bfloat162_rn(y0, y1);
        *(__nv_bfloat162*)(op + 128 * k + 2) = __floats2bfloat162_rn(y2, y3);
    }
}

// ---------------- launch ----------------
extern "C" void kernel_launch(void* const* d_in, const int* in_sizes, int n_in,
                              void* d_out, int out_size)
{
    const float* X    = (const float*)d_in[0];
    const float* Win  = (const float*)d_in[1];
    const float* Wout = (const float*)d_in[2];
    const float* lg   = (const float*)d_in[3];
    const float* lb   = (const float*)d_in[4];
    float* out = (float*)d_out;

    cudaFuncSetAttribute(k_gemm, cudaFuncAttributeMaxDynamicSharedMemorySize, GEMM_SMEM);

    k_convert<<<(E3 * D_) / 4 / 256, 256>>>(Win, E3 * D_);
    k_rotfill<<<128, 256>>>();
    k_layernorm<<<NROWS / 8, 256>>>(X, lg, lb);
    k_gemm<<<dim3(E3 / 128, NROWS / 128), 128, GEMM_SMEM>>>(nullptr, nullptr, 0);
    k_rownorm<<<NROWS / 256, 256>>>();
    k_rowproc<<<NROWS / 16, 256>>>();
    k_reduceA<<<128, 256>>>();
    k_scaleW<<<D_ * D_ / 4 / 256, 256>>>(Wout);
    k_gemm<<<dim3(D_ / 128, NROWS / 128), 128, GEMM_SMEM>>>(X, out, 1);
}